// round 13
// baseline (speedup 1.0000x reference)
#include <cuda_runtime.h>
#include <cuda_bf16.h>
#include <mma.h>
#include <stdint.h>
#include <stddef.h>
#include <math.h>

using namespace nvcuda;

#define NN 200000
#define EE 1600000
#define CC 128
#define NTTS 20000
#define NMOLS 2000

// ---------------- static device scratch ----------------
__device__ float g_t1[(size_t)NN * CC];
__device__ float g_t2[(size_t)NN * CC];
__device__ float g_hs[(size_t)NN * CC];
__device__ float g_hs2[(size_t)NTTS * CC];
__device__ int   g_cnt[NN];
__device__ int   g_rowoff[NN + 1];
__device__ int   g_cursor[NN];
__device__ int   g_bsum[256];
__device__ int   g_col[EE];
__device__ float g_val[EE];
__device__ int   g_ttoff[NTTS + 1];
__device__ int   g_moloff[NMOLS + 1];
__device__ float g_meanbn_tt[(size_t)NTTS * CC];
__device__ float g_gi_tt[(size_t)NTTS * 3 * CC];
__device__ float g_gh_tt[(size_t)NTTS * 3 * CC];
__device__ float g_ttbn[(size_t)NTTS * CC];
__device__ float g_meanbn_mol[(size_t)NMOLS * CC];
__device__ float g_gi_mol[(size_t)NMOLS * 3 * CC];
__device__ float g_gh_mol[(size_t)NMOLS * 3 * CC];
__device__ float g_molout[(size_t)NMOLS * CC];
__device__ float g_ssrc[NN];
__device__ float g_sdst[NTTS];
__device__ float g_vsrc[CC];
__device__ float g_vdst[CC];
__device__ __nv_bfloat16 g_whi[2048 * 128];
__device__ __nv_bfloat16 g_wlo[2048 * 128];
__device__ __nv_bfloat16 g_xhi[(size_t)NN * CC];
__device__ __nv_bfloat16 g_xlo[(size_t)NN * CC];
__device__ __nv_bfloat16 g_phi[(size_t)NTTS * CC];
__device__ __nv_bfloat16 g_plo[(size_t)NTTS * CC];
__device__ __nv_bfloat16 g_ghi[(size_t)NTTS * CC];
__device__ __nv_bfloat16 g_glo[(size_t)NTTS * CC];

#define WR_G0 0
#define WR_G1 128
#define WR_S0 256
#define WR_S1 384
#define WR_IH0 512
#define WR_IH1 896
#define WR_HH0 1280
#define WR_HH1 1664

// ---------------- helpers ----------------
__device__ __forceinline__ uint32_t smem_u32(const void* p) {
    uint32_t a;
    asm("{ .reg .u64 t; cvta.to.shared.u64 t, %1; cvt.u32.u64 %0, t; }" : "=r"(a) : "l"(p));
    return a;
}
__device__ __forceinline__ void cp16(uint32_t saddr, const void* g) {
    asm volatile("cp.async.cg.shared.global [%0], [%1], 16;" :: "r"(saddr), "l"(g));
}
#define CP_COMMIT asm volatile("cp.async.commit_group;" ::: "memory")
#define CP_WAIT(n) asm volatile("cp.async.wait_group %0;" :: "n"(n) : "memory")

__device__ __forceinline__ void write_split(__nv_bfloat16* hi, __nv_bfloat16* lo,
                                            size_t idx, float z) {
    __nv_bfloat16 h = __float2bfloat16(z);
    hi[idx] = h;
    lo[idx] = __float2bfloat16(z - __bfloat162float(h));
}
// packed split store of 4 consecutive channels at idx0 (idx0 % 4 == 0)
__device__ __forceinline__ void write_split4(__nv_bfloat16* hi, __nv_bfloat16* lo,
                                             size_t idx0, float z0, float z1,
                                             float z2, float z3) {
    __nv_bfloat162 h01 = __floats2bfloat162_rn(z0, z1);
    __nv_bfloat162 h23 = __floats2bfloat162_rn(z2, z3);
    __nv_bfloat162 l01 = __floats2bfloat162_rn(z0 - __bfloat162float(h01.x),
                                               z1 - __bfloat162float(h01.y));
    __nv_bfloat162 l23 = __floats2bfloat162_rn(z2 - __bfloat162float(h23.x),
                                               z3 - __bfloat162float(h23.y));
    *reinterpret_cast<uint2*>(hi + idx0) =
        make_uint2(*reinterpret_cast<uint32_t*>(&h01), *reinterpret_cast<uint32_t*>(&h23));
    *reinterpret_cast<uint2*>(lo + idx0) =
        make_uint2(*reinterpret_cast<uint32_t*>(&l01), *reinterpret_cast<uint32_t*>(&l23));
}

// ---------------- weight split ----------------
__global__ void k_wsplit(const float* __restrict__ Wg, const float* __restrict__ Ws,
                         const float* __restrict__ Wih, const float* __restrict__ Whh,
                         __nv_bfloat16* __restrict__ hi, __nv_bfloat16* __restrict__ lo) {
    int idx = blockIdx.x * blockDim.x + threadIdx.x;
    int row = idx >> 7, c = idx & 127;
    float w;
    if (row < 256)       w = Wg[(size_t)row * 128 + c];
    else if (row < 512)  w = Ws[(size_t)(row - 256) * 128 + c];
    else if (row < 1280) w = Wih[(size_t)(row - 512) * 128 + c];
    else                 w = Whh[(size_t)(row - 1280) * 128 + c];
    write_split(hi, lo, idx, w);
}

// ---------------- activation split (node_attr) ----------------
__global__ void k_xsplit(const float* __restrict__ X, __nv_bfloat16* __restrict__ hi,
                         __nv_bfloat16* __restrict__ lo, int n4) {
    int i = blockIdx.x * blockDim.x + threadIdx.x;
    if (i >= n4) return;
    float4 x = reinterpret_cast<const float4*>(X)[i];
    write_split4(hi, lo, (size_t)i * 4, x.x, x.y, x.z, x.w);
}

// ---------------- wmma GEMM (R8 config): Y = X @ W^T, 3-term bf16 split,
// 128x128 tile, 256 threads (8 warps: 2m x 4n), A double-buffered; dual-batch via z ----------------
#define LDA 136
#define TILE_BYTES (128 * LDA * 2)
#define BH_OFF 0
#define BL_OFF TILE_BYTES
#define A_OFF (2 * TILE_BYTES)
#define GEMM_SMEM (A_OFF + 4 * TILE_BYTES)   // 208,896 B

__global__ __launch_bounds__(256) void k_gemm_tc(
    const __nv_bfloat16* __restrict__ Xhi, const __nv_bfloat16* __restrict__ Xlo,
    const __nv_bfloat16* __restrict__ bhi, const __nv_bfloat16* __restrict__ blo,
    float* __restrict__ Y, int M, int Nout,
    const __nv_bfloat16* __restrict__ X2hi, const __nv_bfloat16* __restrict__ X2lo,
    const __nv_bfloat16* __restrict__ b2hi, const __nv_bfloat16* __restrict__ b2lo,
    float* __restrict__ Y2) {
    extern __shared__ char smem[];
    if (blockIdx.z == 1) {
        Xhi = X2hi; Xlo = X2lo; bhi = b2hi; blo = b2lo; Y = Y2;
    }
    __nv_bfloat16* Bh = reinterpret_cast<__nv_bfloat16*>(smem + BH_OFF);
    __nv_bfloat16* Bl = reinterpret_cast<__nv_bfloat16*>(smem + BL_OFF);

    int tid = threadIdx.x, wid = tid >> 5;
    int tn = blockIdx.y;
    int ntiles = (M + 127) >> 7;
    if ((int)blockIdx.x >= ntiles) return;
    uint32_t sb = smem_u32(smem);

    for (int i = tid; i < 128 * 16; i += 256) {
        int r = i >> 4, c = i & 15;
        cp16(sb + BH_OFF + r * (LDA * 2) + c * 16, &bhi[(size_t)(tn * 128 + r) * 128 + c * 8]);
        cp16(sb + BL_OFF + r * (LDA * 2) + c * 16, &blo[(size_t)(tn * 128 + r) * 128 + c * 8]);
    }
    CP_COMMIT;

    auto load_a = [&](int tm, int st) {
        int row0 = tm * 128;
        uint32_t base = sb + A_OFF + st * 2 * TILE_BYTES;
        for (int i = tid; i < 128 * 16; i += 256) {
            int r = i >> 4, c = i & 15;
            int gr = row0 + r;
            if (gr >= M) gr = M - 1;
            cp16(base + r * (LDA * 2) + c * 16, &Xhi[(size_t)gr * 128 + c * 8]);
            cp16(base + TILE_BYTES + r * (LDA * 2) + c * 16, &Xlo[(size_t)gr * 128 + c * 8]);
        }
        CP_COMMIT;
    };

    load_a(blockIdx.x, 0);

    int wm = wid & 1, wn = wid >> 1;
    int st = 0;
    for (int tm = blockIdx.x; tm < ntiles; tm += gridDim.x, st ^= 1) {
        int tmn = tm + gridDim.x;
        if (tmn >= ntiles) tmn = tm;
        load_a(tmn, st ^ 1);
        CP_WAIT(1);
        __syncthreads();

        __nv_bfloat16* Ah = reinterpret_cast<__nv_bfloat16*>(smem + A_OFF + st * 2 * TILE_BYTES);
        __nv_bfloat16* Al = Ah + 128 * LDA;

        wmma::fragment<wmma::accumulator, 16, 16, 16, float> cf[4][2];
#pragma unroll
        for (int i = 0; i < 4; i++)
#pragma unroll
            for (int j = 0; j < 2; j++) wmma::fill_fragment(cf[i][j], 0.f);

        const __nv_bfloat16* Aterm[3] = {Ah, Ah, Al};
        const __nv_bfloat16* Bterm[3] = {Bh, Bl, Bh};
#pragma unroll
        for (int t = 0; t < 3; t++) {
            const __nv_bfloat16* As = Aterm[t];
            const __nv_bfloat16* Bs = Bterm[t];
#pragma unroll
            for (int k0 = 0; k0 < 128; k0 += 16) {
                wmma::fragment<wmma::matrix_a, 16, 16, 16, __nv_bfloat16, wmma::row_major> a[4];
                wmma::fragment<wmma::matrix_b, 16, 16, 16, __nv_bfloat16, wmma::col_major> b[2];
#pragma unroll
                for (int i = 0; i < 4; i++)
                    wmma::load_matrix_sync(a[i], &As[(wm * 64 + i * 16) * LDA + k0], LDA);
#pragma unroll
                for (int j = 0; j < 2; j++)
                    wmma::load_matrix_sync(b[j], &Bs[(wn * 32 + j * 16) * LDA + k0], LDA);
#pragma unroll
                for (int i = 0; i < 4; i++)
#pragma unroll
                    for (int j = 0; j < 2; j++) wmma::mma_sync(cf[i][j], a[i], b[j], cf[i][j]);
            }
        }
        int row0 = tm * 128;
#pragma unroll
        for (int i = 0; i < 4; i++) {
            int row = row0 + wm * 64 + i * 16;
            if (row + 16 <= M) {
#pragma unroll
                for (int j = 0; j < 2; j++)
                    wmma::store_matrix_sync(&Y[(size_t)row * Nout + tn * 128 + wn * 32 + j * 16],
                                            cf[i][j], Nout, wmma::mem_row_major);
            }
        }
        __syncthreads();
    }
}

// ---------------- small helpers ----------------
__device__ __forceinline__ float bn_apply(float x, int idx, int ch,
                                          const float* g, const float* b,
                                          const float* m, const float* v) {
    float sc = g[idx * CC + ch] * rsqrtf(v[idx * CC + ch] + 1e-5f);
    return (x - m[idx * CC + ch]) * sc + b[idx * CC + ch];
}
__device__ __forceinline__ float warp_max(float v) {
#pragma unroll
    for (int o = 16; o > 0; o >>= 1) v = fmaxf(v, __shfl_xor_sync(0xffffffffu, v, o));
    return v;
}
__device__ __forceinline__ float warp_sum(float v) {
#pragma unroll
    for (int o = 16; o > 0; o >>= 1) v += __shfl_xor_sync(0xffffffffu, v, o);
    return v;
}

// ---------------- CSR build ----------------
__global__ void k_zero_int(int* p, int n) {
    int i = blockIdx.x * blockDim.x + threadIdx.x;
    if (i < n) p[i] = 0;
}
__global__ void k_hist(const int* __restrict__ idx0, int* __restrict__ cnt) {
    int e = blockIdx.x * blockDim.x + threadIdx.x;
    if (e < EE) atomicAdd(&cnt[idx0[e]], 1);
}
__global__ void k_scan1(const int* __restrict__ in, int* __restrict__ out,
                        int* __restrict__ bsum, int n) {
    __shared__ int sm[1024];
    int i = blockIdx.x * 1024 + threadIdx.x;
    int v = (i < n) ? in[i] : 0;
    sm[threadIdx.x] = v;
    __syncthreads();
    for (int off = 1; off < 1024; off <<= 1) {
        int t = (threadIdx.x >= off) ? sm[threadIdx.x - off] : 0;
        __syncthreads();
        sm[threadIdx.x] += t;
        __syncthreads();
    }
    if (i < n) out[i] = sm[threadIdx.x] - v;
    if (threadIdx.x == 1023) bsum[blockIdx.x] = sm[1023];
}
__global__ void k_scan2(int* __restrict__ bsum, int nb) {
    __shared__ int sm[256];
    int v = (threadIdx.x < nb) ? bsum[threadIdx.x] : 0;
    sm[threadIdx.x] = v;
    __syncthreads();
    for (int off = 1; off < 256; off <<= 1) {
        int t = (threadIdx.x >= off) ? sm[threadIdx.x - off] : 0;
        __syncthreads();
        sm[threadIdx.x] += t;
        __syncthreads();
    }
    if (threadIdx.x < nb) bsum[threadIdx.x] = sm[threadIdx.x] - v;
}
__global__ void k_scan3(int* __restrict__ out, const int* __restrict__ bsum,
                        int n, int total, int* __restrict__ cursor) {
    int i = blockIdx.x * 1024 + threadIdx.x;
    if (i < n) {
        int v = out[i] + bsum[blockIdx.x];
        out[i] = v;
        cursor[i] = v;
    }
    if (i == 0) out[n] = total;
}
__global__ void k_scatter(const int* __restrict__ adj, const float* __restrict__ aval,
                          int* __restrict__ cursor, int* __restrict__ col,
                          float* __restrict__ val) {
    int e = blockIdx.x * blockDim.x + threadIdx.x;
    if (e >= EE) return;
    int r = adj[e];
    int p = atomicAdd(&cursor[r], 1);
    col[p] = adj[EE + e];
    val[p] = aval[e];
}
__global__ void k_segoff(const int* __restrict__ seg, int n, int nseg, int* __restrict__ off) {
    int i = blockIdx.x * blockDim.x + threadIdx.x;
    if (i >= n) return;
    int s = seg[i];
    int p = (i == 0) ? -1 : seg[i - 1];
    for (int t = p + 1; t <= s; ++t) off[t] = i;
    if (i == n - 1)
        for (int t = s + 1; t <= nseg; ++t) off[t] = n;
}

// ---------------- SpMM (float4 lanes, 4-edge unroll) + bias + BN(+relu)(+BN2) ----------------
__global__ void k_spmm(const float* __restrict__ Xin, float* __restrict__ Yf,
                       __nv_bfloat16* __restrict__ Yhi, __nv_bfloat16* __restrict__ Ylo,
                       const int* __restrict__ rowoff, const int* __restrict__ col,
                       const float* __restrict__ val, const float* __restrict__ bias,
                       const float* __restrict__ vsrc, float* __restrict__ svout,
                       const float* __restrict__ bg, const float* __restrict__ bb,
                       const float* __restrict__ bm, const float* __restrict__ bv,
                       int bnA, int bnB, int M) {
    int gw = (blockIdx.x * blockDim.x + threadIdx.x) >> 5;
    int lane = threadIdx.x & 31;
    if (gw >= M) return;
    int s = rowoff[gw], e = rowoff[gw + 1];
    float4 acc = make_float4(0.f, 0.f, 0.f, 0.f);
    int i = s;
    for (; i + 3 < e; i += 4) {
        int c0 = col[i], c1 = col[i + 1], c2 = col[i + 2], c3 = col[i + 3];
        float v0 = val[i], v1 = val[i + 1], v2 = val[i + 2], v3 = val[i + 3];
        float4 x0 = reinterpret_cast<const float4*>(Xin + (size_t)c0 * CC)[lane];
        float4 x1 = reinterpret_cast<const float4*>(Xin + (size_t)c1 * CC)[lane];
        float4 x2 = reinterpret_cast<const float4*>(Xin + (size_t)c2 * CC)[lane];
        float4 x3 = reinterpret_cast<const float4*>(Xin + (size_t)c3 * CC)[lane];
        acc.x += v0 * x0.x + v1 * x1.x + v2 * x2.x + v3 * x3.x;
        acc.y += v0 * x0.y + v1 * x1.y + v2 * x2.y + v3 * x3.y;
        acc.z += v0 * x0.z + v1 * x1.z + v2 * x2.z + v3 * x3.z;
        acc.w += v0 * x0.w + v1 * x1.w + v2 * x2.w + v3 * x3.w;
    }
    for (; i < e; i++) {
        int c0 = col[i];
        float v0 = val[i];
        float4 x0 = reinterpret_cast<const float4*>(Xin + (size_t)c0 * CC)[lane];
        acc.x += v0 * x0.x; acc.y += v0 * x0.y; acc.z += v0 * x0.z; acc.w += v0 * x0.w;
    }
    int ch0 = lane * 4;
    float z[4] = {acc.x, acc.y, acc.z, acc.w};
    float sdot = 0.f;
#pragma unroll
    for (int j = 0; j < 4; j++) {
        int ch = ch0 + j;
        float t = z[j] + bias[ch];
        t = bn_apply(t, bnA, ch, bg, bb, bm, bv);
        t = fmaxf(t, 0.f);
        if (bnB >= 0) t = bn_apply(t, bnB, ch, bg, bb, bm, bv);
        z[j] = t;
        if (vsrc) sdot += t * vsrc[ch];
    }
    size_t idx0 = (size_t)gw * CC + ch0;
    if (Yf) *reinterpret_cast<float4*>(Yf + idx0) = make_float4(z[0], z[1], z[2], z[3]);
    if (Yhi) write_split4(Yhi, Ylo, idx0, z[0], z[1], z[2], z[3]);
    if (vsrc) {
        sdot = warp_sum(sdot);
        if (lane == 0) svout[gw] = sdot;
    }
}

// ---------------- segment sum pool (f32 input, as R11) + relu + BN ----------------
__global__ void k_segpool(const float* __restrict__ X, float* __restrict__ Yf,
                          __nv_bfloat16* __restrict__ Yhi, __nv_bfloat16* __restrict__ Ylo,
                          const int* __restrict__ off, int nseg,
                          const float* bg, const float* bb, const float* bm,
                          const float* bv, int bi) {
    int gw = (blockIdx.x * blockDim.x + threadIdx.x) >> 5;
    int lane = threadIdx.x & 31;
    if (gw >= nseg) return;
    int s = off[gw], e = off[gw + 1];
    float4 acc = make_float4(0.f, 0.f, 0.f, 0.f);
    for (int i = s; i < e; i++) {
        float4 x = reinterpret_cast<const float4*>(X + (size_t)i * CC)[lane];
        acc.x += x.x; acc.y += x.y; acc.z += x.z; acc.w += x.w;
    }
    int ch0 = lane * 4;
    float z[4] = {acc.x, acc.y, acc.z, acc.w};
#pragma unroll
    for (int j = 0; j < 4; j++)
        z[j] = bn_apply(fmaxf(z[j], 0.f), bi, ch0 + j, bg, bb, bm, bv);
    size_t idx0 = (size_t)gw * CC + ch0;
    *reinterpret_cast<float4*>(Yf + idx0) = make_float4(z[0], z[1], z[2], z[3]);
    write_split4(Yhi, Ylo, idx0, z[0], z[1], z[2], z[3]);
}

// vd[c] = sum_o ad[o] * Wd[o,c]
__global__ void k_vd(const float* __restrict__ Wd, const float* __restrict__ ad,
                     float* __restrict__ vd) {
    int c = threadIdx.x;
    float s = 0.f;
    for (int o = 0; o < CC; o++) s += ad[o] * Wd[o * CC + c];
    vd[c] = s;
}
__global__ void k_rowdot(const float* __restrict__ X, const float* __restrict__ v,
                         float* __restrict__ out, int M) {
    int gw = (blockIdx.x * blockDim.x + threadIdx.x) >> 5;
    int lane = threadIdx.x & 31;
    if (gw >= M) return;
    float4 x = reinterpret_cast<const float4*>(X + (size_t)gw * CC)[lane];
    float4 vv = reinterpret_cast<const float4*>(v)[lane];
    float s = x.x * vv.x + x.y * vv.y + x.z * vv.z + x.w * vv.w;
    s = warp_sum(s);
    if (lane == 0) out[gw] = s;
}

// ---------------- GAT softmax + aggregate (float4) + bias + ELU -> bf16-split out ----------------
__global__ void k_gat(const float* __restrict__ hs, const float* __restrict__ ssrc,
                      const float* __restrict__ sdst, const int* __restrict__ off,
                      const float* __restrict__ bias, __nv_bfloat16* __restrict__ outhi,
                      __nv_bfloat16* __restrict__ outlo, int nseg) {
    int gw = (blockIdx.x * blockDim.x + threadIdx.x) >> 5;
    int lane = threadIdx.x & 31;
    if (gw >= nseg) return;
    int s = off[gw], e = off[gw + 1];
    float sd = sdst[gw];
    float4 acc = make_float4(0.f, 0.f, 0.f, 0.f);
    if (e > s) {
        float mx = -3.402823e38f;
        for (int i = s + lane; i < e; i += 32) {
            float a = ssrc[i] + sd;
            a = a > 0.f ? a : 0.01f * a;
            mx = fmaxf(mx, a);
        }
        mx = warp_max(mx);
        float den = 0.f;
        for (int i = s + lane; i < e; i += 32) {
            float a = ssrc[i] + sd;
            a = a > 0.f ? a : 0.01f * a;
            den += __expf(a - mx);
        }
        den = warp_sum(den);
        float inv = 1.f / den;
        for (int i = s; i < e; i++) {
            float a = ssrc[i] + sd;
            a = a > 0.f ? a : 0.01f * a;
            float w = __expf(a - mx) * inv;
            float4 x = reinterpret_cast<const float4*>(hs + (size_t)i * CC)[lane];
            acc.x += w * x.x; acc.y += w * x.y; acc.z += w * x.z; acc.w += w * x.w;
        }
    }
    int ch0 = lane * 4;
    float z[4] = {acc.x, acc.y, acc.z, acc.w};
#pragma unroll
    for (int j = 0; j < 4; j++) {
        float v = z[j] + bias[ch0 + j];
        z[j] = v > 0.f ? v : (__expf(v) - 1.f);  // ELU
    }
    write_split4(outhi, outlo, (size_t)gw * CC + ch0, z[0], z[1], z[2], z[3]);
}

// ---------------- GRU gates (+ folded biases) + relu + BN(+BN2) ----------------
__global__ void k_gru(const float* __restrict__ gi, const float* __restrict__ gh,
                      const float* __restrict__ h, const float* __restrict__ bih,
                      const float* __restrict__ bhh, float* __restrict__ outf,
                      __nv_bfloat16* __restrict__ outhi, __nv_bfloat16* __restrict__ outlo,
                      int M, const float* bg, const float* bb, const float* bm,
                      const float* bv, int bnA, int bnB) {
    int idx = blockIdx.x * blockDim.x + threadIdx.x;
    if (idx >= M * CC) return;
    int t = idx >> 7, c = idx & 127;
    const float* gir = gi + (size_t)t * 3 * CC;
    const float* ghr = gh + (size_t)t * 3 * CC;
    float r = 1.f / (1.f + __expf(-(gir[c] + bih[c] + ghr[c] + bhh[c])));
    float z = 1.f / (1.f + __expf(-(gir[CC + c] + bih[CC + c] + ghr[CC + c] + bhh[CC + c])));
    float n = tanhf(gir[2 * CC + c] + bih[2 * CC + c] +
                    r * (ghr[2 * CC + c] + bhh[2 * CC + c]));
    float hv = (1.f - z) * n + z * h[idx];
    float y = fmaxf(hv, 0.f);
    y = bn_apply(y, bnA, c, bg, bb, bm, bv);
    if (bnB >= 0) y = bn_apply(y, bnB, c, bg, bb, bm, bv);
    outf[idx] = y;
    if (outhi) write_split(outhi, outlo, idx, y);
}

// ---------------- predictor ----------------
__global__ void k_pred(const float* __restrict__ mol, const float* __restrict__ W1,
                       const float* __restrict__ b1, const float* __restrict__ W2,
                       const float* __restrict__ b2, float* __restrict__ out) {
    __shared__ float xr[CC];
    __shared__ float hr[64];
    int m = blockIdx.x, t = threadIdx.x;
    xr[t] = mol[(size_t)m * CC + t];
    xr[t + 64] = mol[(size_t)m * CC + t + 64];
    __syncthreads();
    float s = b1[t];
    for (int c = 0; c < CC; c++) s += W1[t * CC + c] * xr[c];
    s = fmaxf(s, 0.f);
    hr[t] = s * W2[t];
    __syncthreads();
    for (int off = 32; off > 0; off >>= 1) {
        if (t < off) hr[t] += hr[t + off];
        __syncthreads();
    }
    if (t == 0) out[m] = hr[0] + b2[0];
}

// ---------------- host ----------------
extern "C" void kernel_launch(void* const* d_in, const int* in_sizes, int n_in,
                              void* d_out, int out_size) {
    if (n_in < 24) return;
    const float *node_attr, *adj_value, *W_gcn, *b_gcn, *bg, *bb, *bm, *bv;
    const float *Wsrc, *Wdst, *asrc, *adst, *gbias, *Wih, *Whh, *bih, *bhh;
    const float *pW1, *pb1, *pW2, *pb2;
    const int *adj_index, *ttb, *tgb;
    if (in_sizes[1] == EE) {
        node_attr = (const float*)d_in[0];  adj_value = (const float*)d_in[1];
        W_gcn = (const float*)d_in[2];      b_gcn = (const float*)d_in[3];
        bg = (const float*)d_in[4];         bb = (const float*)d_in[5];
        bm = (const float*)d_in[6];         bv = (const float*)d_in[7];
        Wsrc = (const float*)d_in[8];       Wdst = (const float*)d_in[9];
        asrc = (const float*)d_in[10];      adst = (const float*)d_in[11];
        gbias = (const float*)d_in[12];     Wih = (const float*)d_in[13];
        Whh = (const float*)d_in[14];       bih = (const float*)d_in[15];
        bhh = (const float*)d_in[16];       pW1 = (const float*)d_in[17];
        pb1 = (const float*)d_in[18];       pW2 = (const float*)d_in[19];
        pb2 = (const float*)d_in[20];       adj_index = (const int*)d_in[21];
        ttb = (const int*)d_in[22];         tgb = (const int*)d_in[23];
    } else {
        node_attr = (const float*)d_in[0];  adj_index = (const int*)d_in[1];
        adj_value = (const float*)d_in[2];  ttb = (const int*)d_in[3];
        tgb = (const int*)d_in[4];          W_gcn = (const float*)d_in[5];
        b_gcn = (const float*)d_in[6];      bg = (const float*)d_in[7];
        bb = (const float*)d_in[8];         bm = (const float*)d_in[9];
        bv = (const float*)d_in[10];        Wsrc = (const float*)d_in[11];
        Wdst = (const float*)d_in[12];      asrc = (const float*)d_in[13];
        adst = (const float*)d_in[14];      gbias = (const float*)d_in[15];
        Wih = (const float*)d_in[16];       Whh = (const float*)d_in[17];
        bih = (const float*)d_in[18];       bhh = (const float*)d_in[19];
        pW1 = (const float*)d_in[20];       pb1 = (const float*)d_in[21];
        pW2 = (const float*)d_in[22];       pb2 = (const float*)d_in[23];
    }

    void* p;
    cudaGetSymbolAddress(&p, g_t1);        float* t1 = (float*)p;
    cudaGetSymbolAddress(&p, g_t2);        float* t2 = (float*)p;
    cudaGetSymbolAddress(&p, g_hs);        float* hs = (float*)p;
    cudaGetSymbolAddress(&p, g_hs2);       float* hs2 = (float*)p;
    cudaGetSymbolAddress(&p, g_cnt);       int* cnt = (int*)p;
    cudaGetSymbolAddress(&p, g_rowoff);    int* rowoff = (int*)p;
    cudaGetSymbolAddress(&p, g_cursor);    int* cursor = (int*)p;
    cudaGetSymbolAddress(&p, g_bsum);      int* bsum = (int*)p;
    cudaGetSymbolAddress(&p, g_col);       int* col = (int*)p;
    cudaGetSymbolAddress(&p, g_val);       float* val = (float*)p;
    cudaGetSymbolAddress(&p, g_ttoff);     int* ttoff = (int*)p;
    cudaGetSymbolAddress(&p, g_moloff);    int* moloff = (int*)p;
    cudaGetSymbolAddress(&p, g_meanbn_tt); float* meanbn_tt = (float*)p;
    cudaGetSymbolAddress(&p, g_gi_tt);     float* gi_tt = (float*)p;
    cudaGetSymbolAddress(&p, g_gh_tt);     float* gh_tt = (float*)p;
    cudaGetSymbolAddress(&p, g_ttbn);      float* ttbn = (float*)p;
    cudaGetSymbolAddress(&p, g_meanbn_mol);float* meanbn_mol = (float*)p;
    cudaGetSymbolAddress(&p, g_gi_mol);    float* gi_mol = (float*)p;
    cudaGetSymbolAddress(&p, g_gh_mol);    float* gh_mol = (float*)p;
    cudaGetSymbolAddress(&p, g_molout);    float* molout = (float*)p;
    cudaGetSymbolAddress(&p, g_ssrc);      float* ssrc = (float*)p;
    cudaGetSymbolAddress(&p, g_sdst);      float* sdst = (float*)p;
    cudaGetSymbolAddress(&p, g_vsrc);      float* vsrc = (float*)p;
    cudaGetSymbolAddress(&p, g_vdst);      float* vdst = (float*)p;
    cudaGetSymbolAddress(&p, g_whi);       __nv_bfloat16* whi = (__nv_bfloat16*)p;
    cudaGetSymbolAddress(&p, g_wlo);       __nv_bfloat16* wlo = (__nv_bfloat16*)p;
    cudaGetSymbolAddress(&p, g_xhi);       __nv_bfloat16* xhi = (__nv_bfloat16*)p;
    cudaGetSymbolAddress(&p, g_xlo);       __nv_bfloat16* xlo = (__nv_bfloat16*)p;
    cudaGetSymbolAddress(&p, g_phi);       __nv_bfloat16* phi = (__nv_bfloat16*)p;
    cudaGetSymbolAddress(&p, g_plo);       __nv_bfloat16* plo = (__nv_bfloat16*)p;
    cudaGetSymbolAddress(&p, g_ghi);       __nv_bfloat16* ghi = (__nv_bfloat16*)p;
    cudaGetSymbolAddress(&p, g_glo);       __nv_bfloat16* glo = (__nv_bfloat16*)p;
    float* outp = (float*)d_out;

    static cudaStream_t s1 = nullptr;
    static cudaEvent_t ev[8];
    if (s1 == nullptr) {
        cudaStreamCreateWithFlags(&s1, cudaStreamNonBlocking);
        for (int i = 0; i < 8; i++) cudaEventCreateWithFlags(&ev[i], cudaEventDisableTiming);
    }
    auto fork = [&](int i) {
        cudaEventRecord(ev[i], 0);
        cudaStreamWaitEvent(s1, ev[i], 0);
    };
    auto join = [&](int i) {
        cudaEventRecord(ev[i], s1);
        cudaStreamWaitEvent((cudaStream_t)0, ev[i], 0);
    };

    cudaFuncSetAttribute(k_gemm_tc, cudaFuncAttributeMaxDynamicSharedMemorySize, GEMM_SMEM);

    auto gemm = [&](const __nv_bfloat16* xh, const __nv_bfloat16* xl, int wrow,
                    float* Y, int M, int Nout) {
        int ntiles = (M + 127) / 128;
        int gy = Nout / 128;
        int gxmax = 148 / gy; if (gxmax < 1) gxmax = 1;
        int gx = ntiles < gxmax ? ntiles : gxmax;
        dim3 grid(gx, gy, 1);
        k_gemm_tc<<<grid, 256, GEMM_SMEM>>>(xh, xl, whi + (size_t)wrow * 128,
                                            wlo + (size_t)wrow * 128, Y, M, Nout,
                                            nullptr, nullptr, nullptr, nullptr, nullptr);
    };
    auto gemm2 = [&](const __nv_bfloat16* xh, const __nv_bfloat16* xl, int wrow, float* Y,
                     const __nv_bfloat16* xh2, const __nv_bfloat16* xl2, int wrow2, float* Y2,
                     int M, int Nout) {
        int ntiles = (M + 127) / 128;
        int gy = Nout / 128;
        int gxmax = 148 / (gy * 2); if (gxmax < 1) gxmax = 1;
        int gx = ntiles < gxmax ? ntiles : gxmax;
        dim3 grid(gx, gy, 2);
        k_gemm_tc<<<grid, 256, GEMM_SMEM>>>(xh, xl, whi + (size_t)wrow * 128,
                                            wlo + (size_t)wrow * 128, Y, M, Nout,
                                            xh2, xl2, whi + (size_t)wrow2 * 128,
                                            wlo + (size_t)wrow2 * 128, Y2);
    };

    // ===== phase 1: CSR build (s1)  ||  wsplit+xsplit+gemm0 (main) =====
    fork(0);
    k_zero_int<<<(NN + 255) / 256, 256, 0, s1>>>(cnt, NN);
    k_hist<<<(EE + 255) / 256, 256, 0, s1>>>(adj_index, cnt);
    k_scan1<<<196, 1024, 0, s1>>>(cnt, rowoff, bsum, NN);
    k_scan2<<<1, 256, 0, s1>>>(bsum, 196);
    k_scan3<<<196, 1024, 0, s1>>>(rowoff, bsum, NN, EE, cursor);
    k_scatter<<<(EE + 255) / 256, 256, 0, s1>>>(adj_index, adj_value, cursor, col, val);
    k_segoff<<<(NN + 255) / 256, 256, 0, s1>>>(ttb, NN, NTTS, ttoff);
    k_segoff<<<(NTTS + 255) / 256, 256, 0, s1>>>(tgb, NTTS, NMOLS, moloff);
    k_vd<<<1, 128, 0, s1>>>(Wsrc, asrc, vsrc);
    k_vd<<<1, 128, 0, s1>>>(Wdst, adst, vdst);

    k_wsplit<<<1024, 256>>>(W_gcn, Wsrc, Wih, Whh, whi, wlo);
    k_xsplit<<<(NN * 32 + 255) / 256, 256>>>(node_attr, xhi, xlo, NN * 32);
    gemm(xhi, xlo, WR_G0, t1, NN, 128);
    join(1);

    // ===== GCN layers =====
    k_spmm<<<NN / 8, 256>>>(t1, nullptr, xhi, xlo, rowoff, col, val, b_gcn,
                            nullptr, nullptr, bg, bb, bm, bv, 0, -1, NN);
    gemm(xhi, xlo, WR_G1, t1, NN, 128);
    k_spmm<<<NN / 8, 256>>>(t1, t2, xhi, xlo, rowoff, col, val, b_gcn + CC,
                            vsrc, ssrc, bg, bb, bm, bv, 1, 2, NN);

    // ===== tt stage: segpool+rowdot (s1)  ||  hs GEMM (main) =====
    fork(2);
    k_segpool<<<(NTTS * 32 + 255) / 256, 256, 0, s1>>>(t2, meanbn_tt, phi, plo, ttoff, NTTS,
                                                       bg, bb, bm, bv, 3);
    k_rowdot<<<(NTTS * 32 + 255) / 256, 256, 0, s1>>>(meanbn_tt, vdst, sdst, NTTS);

    gemm(xhi, xlo, WR_S0, hs, NN, 128);
    join(3);

    k_gat<<<(NTTS * 32 + 255) / 256, 256>>>(hs, ssrc, sdst, ttoff, gbias, ghi, glo, NTTS);
    gemm2(ghi, glo, WR_IH0, gi_tt, phi, plo, WR_HH0, gh_tt, NTTS, 384);
    k_gru<<<(NTTS * CC + 255) / 256, 256>>>(gi_tt, gh_tt, meanbn_tt, bih, bhh,
                                            ttbn, ghi, glo, NTTS, bg, bb, bm, bv, 4, 5);

    // ===== mol stage: segpool+vd+rowdots (s1)  ||  hs2 GEMM (main) =====
    fork(4);
    k_vd<<<1, 128, 0, s1>>>(Wsrc + CC * CC, asrc + CC, vsrc);
    k_vd<<<1, 128, 0, s1>>>(Wdst + CC * CC, adst + CC, vdst);
    k_segpool<<<(NMOLS * 32 + 255) / 256, 256, 0, s1>>>(ttbn, meanbn_mol, phi, plo, moloff,
                                                        NMOLS, bg, bb, bm, bv, 6);
    k_rowdot<<<(NTTS * 32 + 255) / 256, 256, 0, s1>>>(ttbn, vsrc, ssrc, NTTS);
    k_rowdot<<<(NMOLS * 32 + 255) / 256, 256, 0, s1>>>(meanbn_mol, vdst, sdst, NMOLS);

    gemm(ghi, glo, WR_S1, hs2, NTTS, 128);
    join(5);

    k_gat<<<(NMOLS * 32 + 255) / 256, 256>>>(hs2, ssrc, sdst, moloff, gbias + CC,
                                             ghi, glo, NMOLS);
    gemm2(ghi, glo, WR_IH1, gi_mol, phi, plo, WR_HH1, gh_mol, NMOLS, 384);
    k_gru<<<(NMOLS * CC + 255) / 256, 256>>>(gi_mol, gh_mol, meanbn_mol, bih + 3 * CC,
                                             bhh + 3 * CC, molout, nullptr, nullptr,
                                             NMOLS, bg, bb, bm, bv, 7, -1);

    // predictor
    k_pred<<<NMOLS, 64>>>(molout, pW1, pb1, pW2, pb2, outp);
}

// round 14
// speedup vs baseline: 1.0370x; 1.0370x over previous
#include <cuda_runtime.h>
#include <cuda_bf16.h>
#include <mma.h>
#include <stdint.h>
#include <stddef.h>
#include <math.h>

using namespace nvcuda;

#define NN 200000
#define EE 1600000
#define CC 128
#define NTTS 20000
#define NMOLS 2000

// ---------------- static device scratch ----------------
__device__ float g_t1[(size_t)NN * CC];
__device__ float g_t2[(size_t)NN * CC];
__device__ float g_hs[(size_t)NN * CC];
__device__ float g_hs2[(size_t)NTTS * CC];
__device__ int   g_cnt[NN];
__device__ int   g_rowoff[NN + 1];
__device__ int   g_cursor[NN];
__device__ int   g_bsum[256];
__device__ int   g_col[EE];
__device__ float g_val[EE];
__device__ int   g_ttoff[NTTS + 1];
__device__ int   g_moloff[NMOLS + 1];
__device__ float g_meanbn_tt[(size_t)NTTS * CC];
__device__ float g_gi_tt[(size_t)NTTS * 3 * CC];
__device__ float g_gh_tt[(size_t)NTTS * 3 * CC];
__device__ float g_ttbn[(size_t)NTTS * CC];
__device__ float g_meanbn_mol[(size_t)NMOLS * CC];
__device__ float g_gi_mol[(size_t)NMOLS * 3 * CC];
__device__ float g_gh_mol[(size_t)NMOLS * 3 * CC];
__device__ float g_molout[(size_t)NMOLS * CC];
__device__ float g_ssrc[NN];
__device__ float g_sdst[NTTS];
__device__ float g_vsrc[CC];
__device__ float g_vdst[CC];
__device__ __nv_bfloat16 g_whi[2048 * 128];
__device__ __nv_bfloat16 g_wlo[2048 * 128];
__device__ __nv_bfloat16 g_xhi[(size_t)NN * CC];
__device__ __nv_bfloat16 g_xlo[(size_t)NN * CC];
__device__ __nv_bfloat16 g_phi[(size_t)NTTS * CC];
__device__ __nv_bfloat16 g_plo[(size_t)NTTS * CC];
__device__ __nv_bfloat16 g_ghi[(size_t)NTTS * CC];
__device__ __nv_bfloat16 g_glo[(size_t)NTTS * CC];

#define WR_G0 0
#define WR_G1 128
#define WR_S0 256
#define WR_S1 384
#define WR_IH0 512
#define WR_IH1 896
#define WR_HH0 1280
#define WR_HH1 1664

// ---------------- helpers ----------------
__device__ __forceinline__ uint32_t smem_u32(const void* p) {
    uint32_t a;
    asm("{ .reg .u64 t; cvta.to.shared.u64 t, %1; cvt.u32.u64 %0, t; }" : "=r"(a) : "l"(p));
    return a;
}
__device__ __forceinline__ void cp16(uint32_t saddr, const void* g) {
    asm volatile("cp.async.cg.shared.global [%0], [%1], 16;" :: "r"(saddr), "l"(g));
}
#define CP_COMMIT asm volatile("cp.async.commit_group;" ::: "memory")
#define CP_WAIT(n) asm volatile("cp.async.wait_group %0;" :: "n"(n) : "memory")

__device__ __forceinline__ void write_split(__nv_bfloat16* hi, __nv_bfloat16* lo,
                                            size_t idx, float z) {
    __nv_bfloat16 h = __float2bfloat16(z);
    hi[idx] = h;
    lo[idx] = __float2bfloat16(z - __bfloat162float(h));
}
// packed split store of 4 consecutive channels at idx0 (idx0 % 4 == 0)
__device__ __forceinline__ void write_split4(__nv_bfloat16* hi, __nv_bfloat16* lo,
                                             size_t idx0, float z0, float z1,
                                             float z2, float z3) {
    __nv_bfloat162 h01 = __floats2bfloat162_rn(z0, z1);
    __nv_bfloat162 h23 = __floats2bfloat162_rn(z2, z3);
    __nv_bfloat162 l01 = __floats2bfloat162_rn(z0 - __bfloat162float(h01.x),
                                               z1 - __bfloat162float(h01.y));
    __nv_bfloat162 l23 = __floats2bfloat162_rn(z2 - __bfloat162float(h23.x),
                                               z3 - __bfloat162float(h23.y));
    *reinterpret_cast<uint2*>(hi + idx0) =
        make_uint2(*reinterpret_cast<uint32_t*>(&h01), *reinterpret_cast<uint32_t*>(&h23));
    *reinterpret_cast<uint2*>(lo + idx0) =
        make_uint2(*reinterpret_cast<uint32_t*>(&l01), *reinterpret_cast<uint32_t*>(&l23));
}

// ---------------- weight split ----------------
__global__ void k_wsplit(const float* __restrict__ Wg, const float* __restrict__ Ws,
                         const float* __restrict__ Wih, const float* __restrict__ Whh,
                         __nv_bfloat16* __restrict__ hi, __nv_bfloat16* __restrict__ lo) {
    int idx = blockIdx.x * blockDim.x + threadIdx.x;
    int row = idx >> 7, c = idx & 127;
    float w;
    if (row < 256)       w = Wg[(size_t)row * 128 + c];
    else if (row < 512)  w = Ws[(size_t)(row - 256) * 128 + c];
    else if (row < 1280) w = Wih[(size_t)(row - 512) * 128 + c];
    else                 w = Whh[(size_t)(row - 1280) * 128 + c];
    write_split(hi, lo, idx, w);
}

// ---------------- activation split (node_attr) ----------------
__global__ void k_xsplit(const float* __restrict__ X, __nv_bfloat16* __restrict__ hi,
                         __nv_bfloat16* __restrict__ lo, int n4) {
    int i = blockIdx.x * blockDim.x + threadIdx.x;
    if (i >= n4) return;
    float4 x = reinterpret_cast<const float4*>(X)[i];
    write_split4(hi, lo, (size_t)i * 4, x.x, x.y, x.z, x.w);
}

// ---------------- wmma GEMM (R8 config): Y = X @ W^T, 3-term bf16 split,
// 128x128 tile, 256 threads (8 warps: 2m x 4n), A double-buffered; dual-batch via z ----------------
#define LDA 136
#define TILE_BYTES (128 * LDA * 2)
#define BH_OFF 0
#define BL_OFF TILE_BYTES
#define A_OFF (2 * TILE_BYTES)
#define GEMM_SMEM (A_OFF + 4 * TILE_BYTES)   // 208,896 B

__global__ __launch_bounds__(256) void k_gemm_tc(
    const __nv_bfloat16* __restrict__ Xhi, const __nv_bfloat16* __restrict__ Xlo,
    const __nv_bfloat16* __restrict__ bhi, const __nv_bfloat16* __restrict__ blo,
    float* __restrict__ Y, int M, int Nout,
    const __nv_bfloat16* __restrict__ X2hi, const __nv_bfloat16* __restrict__ X2lo,
    const __nv_bfloat16* __restrict__ b2hi, const __nv_bfloat16* __restrict__ b2lo,
    float* __restrict__ Y2) {
    extern __shared__ char smem[];
    if (blockIdx.z == 1) {
        Xhi = X2hi; Xlo = X2lo; bhi = b2hi; blo = b2lo; Y = Y2;
    }
    __nv_bfloat16* Bh = reinterpret_cast<__nv_bfloat16*>(smem + BH_OFF);
    __nv_bfloat16* Bl = reinterpret_cast<__nv_bfloat16*>(smem + BL_OFF);

    int tid = threadIdx.x, wid = tid >> 5;
    int tn = blockIdx.y;
    int ntiles = (M + 127) >> 7;
    if ((int)blockIdx.x >= ntiles) return;
    uint32_t sb = smem_u32(smem);

    for (int i = tid; i < 128 * 16; i += 256) {
        int r = i >> 4, c = i & 15;
        cp16(sb + BH_OFF + r * (LDA * 2) + c * 16, &bhi[(size_t)(tn * 128 + r) * 128 + c * 8]);
        cp16(sb + BL_OFF + r * (LDA * 2) + c * 16, &blo[(size_t)(tn * 128 + r) * 128 + c * 8]);
    }
    CP_COMMIT;

    auto load_a = [&](int tm, int st) {
        int row0 = tm * 128;
        uint32_t base = sb + A_OFF + st * 2 * TILE_BYTES;
        for (int i = tid; i < 128 * 16; i += 256) {
            int r = i >> 4, c = i & 15;
            int gr = row0 + r;
            if (gr >= M) gr = M - 1;
            cp16(base + r * (LDA * 2) + c * 16, &Xhi[(size_t)gr * 128 + c * 8]);
            cp16(base + TILE_BYTES + r * (LDA * 2) + c * 16, &Xlo[(size_t)gr * 128 + c * 8]);
        }
        CP_COMMIT;
    };

    load_a(blockIdx.x, 0);

    int wm = wid & 1, wn = wid >> 1;
    int st = 0;
    for (int tm = blockIdx.x; tm < ntiles; tm += gridDim.x, st ^= 1) {
        int tmn = tm + gridDim.x;
        if (tmn < ntiles) {
            load_a(tmn, st ^ 1);   // next stage in flight
            CP_WAIT(1);            // current stage (and B) complete
        } else {
            CP_WAIT(0);            // last iteration: drain everything
        }
        __syncthreads();

        __nv_bfloat16* Ah = reinterpret_cast<__nv_bfloat16*>(smem + A_OFF + st * 2 * TILE_BYTES);
        __nv_bfloat16* Al = Ah + 128 * LDA;

        wmma::fragment<wmma::accumulator, 16, 16, 16, float> cf[4][2];
#pragma unroll
        for (int i = 0; i < 4; i++)
#pragma unroll
            for (int j = 0; j < 2; j++) wmma::fill_fragment(cf[i][j], 0.f);

        const __nv_bfloat16* Aterm[3] = {Ah, Ah, Al};
        const __nv_bfloat16* Bterm[3] = {Bh, Bl, Bh};
#pragma unroll
        for (int t = 0; t < 3; t++) {
            const __nv_bfloat16* As = Aterm[t];
            const __nv_bfloat16* Bs = Bterm[t];
#pragma unroll
            for (int k0 = 0; k0 < 128; k0 += 16) {
                wmma::fragment<wmma::matrix_a, 16, 16, 16, __nv_bfloat16, wmma::row_major> a[4];
                wmma::fragment<wmma::matrix_b, 16, 16, 16, __nv_bfloat16, wmma::col_major> b[2];
#pragma unroll
                for (int i = 0; i < 4; i++)
                    wmma::load_matrix_sync(a[i], &As[(wm * 64 + i * 16) * LDA + k0], LDA);
#pragma unroll
                for (int j = 0; j < 2; j++)
                    wmma::load_matrix_sync(b[j], &Bs[(wn * 32 + j * 16) * LDA + k0], LDA);
#pragma unroll
                for (int i = 0; i < 4; i++)
#pragma unroll
                    for (int j = 0; j < 2; j++) wmma::mma_sync(cf[i][j], a[i], b[j], cf[i][j]);
            }
        }
        int row0 = tm * 128;
#pragma unroll
        for (int i = 0; i < 4; i++) {
            int row = row0 + wm * 64 + i * 16;
            if (row + 16 <= M) {
#pragma unroll
                for (int j = 0; j < 2; j++)
                    wmma::store_matrix_sync(&Y[(size_t)row * Nout + tn * 128 + wn * 32 + j * 16],
                                            cf[i][j], Nout, wmma::mem_row_major);
            }
        }
        __syncthreads();
    }
}

// ---------------- small helpers ----------------
__device__ __forceinline__ float bn_apply(float x, int idx, int ch,
                                          const float* g, const float* b,
                                          const float* m, const float* v) {
    float sc = g[idx * CC + ch] * rsqrtf(v[idx * CC + ch] + 1e-5f);
    return (x - m[idx * CC + ch]) * sc + b[idx * CC + ch];
}
__device__ __forceinline__ float warp_max(float v) {
#pragma unroll
    for (int o = 16; o > 0; o >>= 1) v = fmaxf(v, __shfl_xor_sync(0xffffffffu, v, o));
    return v;
}
__device__ __forceinline__ float warp_sum(float v) {
#pragma unroll
    for (int o = 16; o > 0; o >>= 1) v += __shfl_xor_sync(0xffffffffu, v, o);
    return v;
}

// ---------------- CSR build ----------------
__global__ void k_zero_int(int* p, int n) {
    int i = blockIdx.x * blockDim.x + threadIdx.x;
    if (i < n) p[i] = 0;
}
__global__ void k_hist(const int* __restrict__ idx0, int* __restrict__ cnt) {
    int e = blockIdx.x * blockDim.x + threadIdx.x;
    if (e < EE) atomicAdd(&cnt[idx0[e]], 1);
}
__global__ void k_scan1(const int* __restrict__ in, int* __restrict__ out,
                        int* __restrict__ bsum, int n) {
    __shared__ int sm[1024];
    int i = blockIdx.x * 1024 + threadIdx.x;
    int v = (i < n) ? in[i] : 0;
    sm[threadIdx.x] = v;
    __syncthreads();
    for (int off = 1; off < 1024; off <<= 1) {
        int t = (threadIdx.x >= off) ? sm[threadIdx.x - off] : 0;
        __syncthreads();
        sm[threadIdx.x] += t;
        __syncthreads();
    }
    if (i < n) out[i] = sm[threadIdx.x] - v;
    if (threadIdx.x == 1023) bsum[blockIdx.x] = sm[1023];
}
__global__ void k_scan2(int* __restrict__ bsum, int nb) {
    __shared__ int sm[256];
    int v = (threadIdx.x < nb) ? bsum[threadIdx.x] : 0;
    sm[threadIdx.x] = v;
    __syncthreads();
    for (int off = 1; off < 256; off <<= 1) {
        int t = (threadIdx.x >= off) ? sm[threadIdx.x - off] : 0;
        __syncthreads();
        sm[threadIdx.x] += t;
        __syncthreads();
    }
    if (threadIdx.x < nb) bsum[threadIdx.x] = sm[threadIdx.x] - v;
}
__global__ void k_scan3(int* __restrict__ out, const int* __restrict__ bsum,
                        int n, int total, int* __restrict__ cursor) {
    int i = blockIdx.x * 1024 + threadIdx.x;
    if (i < n) {
        int v = out[i] + bsum[blockIdx.x];
        out[i] = v;
        cursor[i] = v;
    }
    if (i == 0) out[n] = total;
}
__global__ void k_scatter(const int* __restrict__ adj, const float* __restrict__ aval,
                          int* __restrict__ cursor, int* __restrict__ col,
                          float* __restrict__ val) {
    int e = blockIdx.x * blockDim.x + threadIdx.x;
    if (e >= EE) return;
    int r = adj[e];
    int p = atomicAdd(&cursor[r], 1);
    col[p] = adj[EE + e];
    val[p] = aval[e];
}
__global__ void k_segoff(const int* __restrict__ seg, int n, int nseg, int* __restrict__ off) {
    int i = blockIdx.x * blockDim.x + threadIdx.x;
    if (i >= n) return;
    int s = seg[i];
    int p = (i == 0) ? -1 : seg[i - 1];
    for (int t = p + 1; t <= s; ++t) off[t] = i;
    if (i == n - 1)
        for (int t = s + 1; t <= nseg; ++t) off[t] = n;
}

// ---------------- SpMM (strided lanes, 4-edge unroll) + bias + BN(+relu)(+BN2) ----------------
__global__ void k_spmm(const float* __restrict__ Xin, float* __restrict__ Yf,
                       __nv_bfloat16* __restrict__ Yhi, __nv_bfloat16* __restrict__ Ylo,
                       const int* __restrict__ rowoff, const int* __restrict__ col,
                       const float* __restrict__ val, const float* __restrict__ bias,
                       const float* __restrict__ vsrc, float* __restrict__ svout,
                       const float* __restrict__ bg, const float* __restrict__ bb,
                       const float* __restrict__ bm, const float* __restrict__ bv,
                       int bnA, int bnB, int M) {
    int gw = (blockIdx.x * blockDim.x + threadIdx.x) >> 5;
    int lane = threadIdx.x & 31;
    if (gw >= M) return;
    int s = rowoff[gw], e = rowoff[gw + 1];
    float acc[4] = {0.f, 0.f, 0.f, 0.f};
    int i = s;
    for (; i + 3 < e; i += 4) {
        int c0 = col[i], c1 = col[i + 1], c2 = col[i + 2], c3 = col[i + 3];
        float v0 = val[i], v1 = val[i + 1], v2 = val[i + 2], v3 = val[i + 3];
        const float* x0 = Xin + (size_t)c0 * CC;
        const float* x1 = Xin + (size_t)c1 * CC;
        const float* x2 = Xin + (size_t)c2 * CC;
        const float* x3 = Xin + (size_t)c3 * CC;
#pragma unroll
        for (int j = 0; j < 4; j++)
            acc[j] += v0 * x0[lane + 32 * j] + v1 * x1[lane + 32 * j] +
                      v2 * x2[lane + 32 * j] + v3 * x3[lane + 32 * j];
    }
    for (; i < e; i++) {
        int c0 = col[i];
        float v0 = val[i];
        const float* x0 = Xin + (size_t)c0 * CC;
#pragma unroll
        for (int j = 0; j < 4; j++) acc[j] += v0 * x0[lane + 32 * j];
    }
    float sdot = 0.f;
#pragma unroll
    for (int j = 0; j < 4; j++) {
        int ch = lane + 32 * j;
        float z = acc[j] + bias[ch];
        z = bn_apply(z, bnA, ch, bg, bb, bm, bv);
        z = fmaxf(z, 0.f);
        if (bnB >= 0) z = bn_apply(z, bnB, ch, bg, bb, bm, bv);
        size_t idx = (size_t)gw * CC + ch;
        if (Yf) Yf[idx] = z;
        if (Yhi) write_split(Yhi, Ylo, idx, z);
        if (vsrc) sdot += z * vsrc[ch];
    }
    if (vsrc) {
        sdot = warp_sum(sdot);
        if (lane == 0) svout[gw] = sdot;
    }
}

// ---------------- segment sum pool + relu + BN; f32 + bf16-split out ----------------
__global__ void k_segpool(const float* __restrict__ X, float* __restrict__ Yf,
                          __nv_bfloat16* __restrict__ Yhi, __nv_bfloat16* __restrict__ Ylo,
                          const int* __restrict__ off, int nseg,
                          const float* bg, const float* bb, const float* bm,
                          const float* bv, int bi) {
    int gw = (blockIdx.x * blockDim.x + threadIdx.x) >> 5;
    int lane = threadIdx.x & 31;
    if (gw >= nseg) return;
    int s = off[gw], e = off[gw + 1];
    float acc[4] = {0.f, 0.f, 0.f, 0.f};
    for (int i = s; i < e; i++) {
        const float* xr = X + (size_t)i * CC;
#pragma unroll
        for (int j = 0; j < 4; j++) acc[j] += xr[lane + 32 * j];
    }
#pragma unroll
    for (int j = 0; j < 4; j++) {
        int ch = lane + 32 * j;
        float z = bn_apply(fmaxf(acc[j], 0.f), bi, ch, bg, bb, bm, bv);
        size_t idx = (size_t)gw * CC + ch;
        Yf[idx] = z;
        write_split(Yhi, Ylo, idx, z);
    }
}

// vd[c] = sum_o ad[o] * Wd[o,c]
__global__ void k_vd(const float* __restrict__ Wd, const float* __restrict__ ad,
                     float* __restrict__ vd) {
    int c = threadIdx.x;
    float s = 0.f;
    for (int o = 0; o < CC; o++) s += ad[o] * Wd[o * CC + c];
    vd[c] = s;
}
__global__ void k_rowdot(const float* __restrict__ X, const float* __restrict__ v,
                         float* __restrict__ out, int M) {
    int gw = (blockIdx.x * blockDim.x + threadIdx.x) >> 5;
    int lane = threadIdx.x & 31;
    if (gw >= M) return;
    const float* xr = X + (size_t)gw * CC;
    float s = 0.f;
#pragma unroll
    for (int j = 0; j < 4; j++) s += xr[lane + 32 * j] * v[lane + 32 * j];
    s = warp_sum(s);
    if (lane == 0) out[gw] = s;
}

// ---------------- GAT softmax + aggregate + bias + ELU -> bf16-split out ----------------
__global__ void k_gat(const float* __restrict__ hs, const float* __restrict__ ssrc,
                      const float* __restrict__ sdst, const int* __restrict__ off,
                      const float* __restrict__ bias, __nv_bfloat16* __restrict__ outhi,
                      __nv_bfloat16* __restrict__ outlo, int nseg) {
    int gw = (blockIdx.x * blockDim.x + threadIdx.x) >> 5;
    int lane = threadIdx.x & 31;
    if (gw >= nseg) return;
    int s = off[gw], e = off[gw + 1];
    float sd = sdst[gw];
    float acc[4] = {0.f, 0.f, 0.f, 0.f};
    if (e > s) {
        float mx = -3.402823e38f;
        for (int i = s + lane; i < e; i += 32) {
            float a = ssrc[i] + sd;
            a = a > 0.f ? a : 0.01f * a;
            mx = fmaxf(mx, a);
        }
        mx = warp_max(mx);
        float den = 0.f;
        for (int i = s + lane; i < e; i += 32) {
            float a = ssrc[i] + sd;
            a = a > 0.f ? a : 0.01f * a;
            den += __expf(a - mx);
        }
        den = warp_sum(den);
        float inv = 1.f / den;
        for (int i = s; i < e; i++) {
            float a = ssrc[i] + sd;
            a = a > 0.f ? a : 0.01f * a;
            float w = __expf(a - mx) * inv;
            const float* hr = hs + (size_t)i * CC;
#pragma unroll
            for (int j = 0; j < 4; j++) acc[j] += w * hr[lane + 32 * j];
        }
    }
#pragma unroll
    for (int j = 0; j < 4; j++) {
        int ch = lane + 32 * j;
        float v = acc[j] + bias[ch];
        v = v > 0.f ? v : (__expf(v) - 1.f);  // ELU
        write_split(outhi, outlo, (size_t)gw * CC + ch, v);
    }
}

// ---------------- GRU gates (+ folded biases) + relu + BN(+BN2) ----------------
__global__ void k_gru(const float* __restrict__ gi, const float* __restrict__ gh,
                      const float* __restrict__ h, const float* __restrict__ bih,
                      const float* __restrict__ bhh, float* __restrict__ outf,
                      __nv_bfloat16* __restrict__ outhi, __nv_bfloat16* __restrict__ outlo,
                      int M, const float* bg, const float* bb, const float* bm,
                      const float* bv, int bnA, int bnB) {
    int idx = blockIdx.x * blockDim.x + threadIdx.x;
    if (idx >= M * CC) return;
    int t = idx >> 7, c = idx & 127;
    const float* gir = gi + (size_t)t * 3 * CC;
    const float* ghr = gh + (size_t)t * 3 * CC;
    float r = 1.f / (1.f + __expf(-(gir[c] + bih[c] + ghr[c] + bhh[c])));
    float z = 1.f / (1.f + __expf(-(gir[CC + c] + bih[CC + c] + ghr[CC + c] + bhh[CC + c])));
    float n = tanhf(gir[2 * CC + c] + bih[2 * CC + c] +
                    r * (ghr[2 * CC + c] + bhh[2 * CC + c]));
    float hv = (1.f - z) * n + z * h[idx];
    float y = fmaxf(hv, 0.f);
    y = bn_apply(y, bnA, c, bg, bb, bm, bv);
    if (bnB >= 0) y = bn_apply(y, bnB, c, bg, bb, bm, bv);
    outf[idx] = y;
    if (outhi) write_split(outhi, outlo, idx, y);
}

// ---------------- predictor ----------------
__global__ void k_pred(const float* __restrict__ mol, const float* __restrict__ W1,
                       const float* __restrict__ b1, const float* __restrict__ W2,
                       const float* __restrict__ b2, float* __restrict__ out) {
    __shared__ float xr[CC];
    __shared__ float hr[64];
    int m = blockIdx.x, t = threadIdx.x;
    xr[t] = mol[(size_t)m * CC + t];
    xr[t + 64] = mol[(size_t)m * CC + t + 64];
    __syncthreads();
    float s = b1[t];
    for (int c = 0; c < CC; c++) s += W1[t * CC + c] * xr[c];
    s = fmaxf(s, 0.f);
    hr[t] = s * W2[t];
    __syncthreads();
    for (int off = 32; off > 0; off >>= 1) {
        if (t < off) hr[t] += hr[t + off];
        __syncthreads();
    }
    if (t == 0) out[m] = hr[0] + b2[0];
}

// ---------------- host ----------------
extern "C" void kernel_launch(void* const* d_in, const int* in_sizes, int n_in,
                              void* d_out, int out_size) {
    if (n_in < 24) return;
    const float *node_attr, *adj_value, *W_gcn, *b_gcn, *bg, *bb, *bm, *bv;
    const float *Wsrc, *Wdst, *asrc, *adst, *gbias, *Wih, *Whh, *bih, *bhh;
    const float *pW1, *pb1, *pW2, *pb2;
    const int *adj_index, *ttb, *tgb;
    if (in_sizes[1] == EE) {
        node_attr = (const float*)d_in[0];  adj_value = (const float*)d_in[1];
        W_gcn = (const float*)d_in[2];      b_gcn = (const float*)d_in[3];
        bg = (const float*)d_in[4];         bb = (const float*)d_in[5];
        bm = (const float*)d_in[6];         bv = (const float*)d_in[7];
        Wsrc = (const float*)d_in[8];       Wdst = (const float*)d_in[9];
        asrc = (const float*)d_in[10];      adst = (const float*)d_in[11];
        gbias = (const float*)d_in[12];     Wih = (const float*)d_in[13];
        Whh = (const float*)d_in[14];       bih = (const float*)d_in[15];
        bhh = (const float*)d_in[16];       pW1 = (const float*)d_in[17];
        pb1 = (const float*)d_in[18];       pW2 = (const float*)d_in[19];
        pb2 = (const float*)d_in[20];       adj_index = (const int*)d_in[21];
        ttb = (const int*)d_in[22];         tgb = (const int*)d_in[23];
    } else {
        node_attr = (const float*)d_in[0];  adj_index = (const int*)d_in[1];
        adj_value = (const float*)d_in[2];  ttb = (const int*)d_in[3];
        tgb = (const int*)d_in[4];          W_gcn = (const float*)d_in[5];
        b_gcn = (const float*)d_in[6];      bg = (const float*)d_in[7];
        bb = (const float*)d_in[8];         bm = (const float*)d_in[9];
        bv = (const float*)d_in[10];        Wsrc = (const float*)d_in[11];
        Wdst = (const float*)d_in[12];      asrc = (const float*)d_in[13];
        adst = (const float*)d_in[14];      gbias = (const float*)d_in[15];
        Wih = (const float*)d_in[16];       Whh = (const float*)d_in[17];
        bih = (const float*)d_in[18];       bhh = (const float*)d_in[19];
        pW1 = (const float*)d_in[20];       pb1 = (const float*)d_in[21];
        pW2 = (const float*)d_in[22];       pb2 = (const float*)d_in[23];
    }

    void* p;
    cudaGetSymbolAddress(&p, g_t1);        float* t1 = (float*)p;
    cudaGetSymbolAddress(&p, g_t2);        float* t2 = (float*)p;
    cudaGetSymbolAddress(&p, g_hs);        float* hs = (float*)p;
    cudaGetSymbolAddress(&p, g_hs2);       float* hs2 = (float*)p;
    cudaGetSymbolAddress(&p, g_cnt);       int* cnt = (int*)p;
    cudaGetSymbolAddress(&p, g_rowoff);    int* rowoff = (int*)p;
    cudaGetSymbolAddress(&p, g_cursor);    int* cursor = (int*)p;
    cudaGetSymbolAddress(&p, g_bsum);      int* bsum = (int*)p;
    cudaGetSymbolAddress(&p, g_col);       int* col = (int*)p;
    cudaGetSymbolAddress(&p, g_val);       float* val = (float*)p;
    cudaGetSymbolAddress(&p, g_ttoff);     int* ttoff = (int*)p;
    cudaGetSymbolAddress(&p, g_moloff);    int* moloff = (int*)p;
    cudaGetSymbolAddress(&p, g_meanbn_tt); float* meanbn_tt = (float*)p;
    cudaGetSymbolAddress(&p, g_gi_tt);     float* gi_tt = (float*)p;
    cudaGetSymbolAddress(&p, g_gh_tt);     float* gh_tt = (float*)p;
    cudaGetSymbolAddress(&p, g_ttbn);      float* ttbn = (float*)p;
    cudaGetSymbolAddress(&p, g_meanbn_mol);float* meanbn_mol = (float*)p;
    cudaGetSymbolAddress(&p, g_gi_mol);    float* gi_mol = (float*)p;
    cudaGetSymbolAddress(&p, g_gh_mol);    float* gh_mol = (float*)p;
    cudaGetSymbolAddress(&p, g_molout);    float* molout = (float*)p;
    cudaGetSymbolAddress(&p, g_ssrc);      float* ssrc = (float*)p;
    cudaGetSymbolAddress(&p, g_sdst);      float* sdst = (float*)p;
    cudaGetSymbolAddress(&p, g_vsrc);      float* vsrc = (float*)p;
    cudaGetSymbolAddress(&p, g_vdst);      float* vdst = (float*)p;
    cudaGetSymbolAddress(&p, g_whi);       __nv_bfloat16* whi = (__nv_bfloat16*)p;
    cudaGetSymbolAddress(&p, g_wlo);       __nv_bfloat16* wlo = (__nv_bfloat16*)p;
    cudaGetSymbolAddress(&p, g_xhi);       __nv_bfloat16* xhi = (__nv_bfloat16*)p;
    cudaGetSymbolAddress(&p, g_xlo);       __nv_bfloat16* xlo = (__nv_bfloat16*)p;
    cudaGetSymbolAddress(&p, g_phi);       __nv_bfloat16* phi = (__nv_bfloat16*)p;
    cudaGetSymbolAddress(&p, g_plo);       __nv_bfloat16* plo = (__nv_bfloat16*)p;
    cudaGetSymbolAddress(&p, g_ghi);       __nv_bfloat16* ghi = (__nv_bfloat16*)p;
    cudaGetSymbolAddress(&p, g_glo);       __nv_bfloat16* glo = (__nv_bfloat16*)p;
    float* outp = (float*)d_out;

    static cudaStream_t s1 = nullptr;
    static cudaEvent_t ev[8];
    if (s1 == nullptr) {
        cudaStreamCreateWithFlags(&s1, cudaStreamNonBlocking);
        for (int i = 0; i < 8; i++) cudaEventCreateWithFlags(&ev[i], cudaEventDisableTiming);
    }
    auto fork = [&](int i) {
        cudaEventRecord(ev[i], 0);
        cudaStreamWaitEvent(s1, ev[i], 0);
    };
    auto join = [&](int i) {
        cudaEventRecord(ev[i], s1);
        cudaStreamWaitEvent((cudaStream_t)0, ev[i], 0);
    };

    cudaFuncSetAttribute(k_gemm_tc, cudaFuncAttributeMaxDynamicSharedMemorySize, GEMM_SMEM);

    auto gemm = [&](const __nv_bfloat16* xh, const __nv_bfloat16* xl, int wrow,
                    float* Y, int M, int Nout) {
        int ntiles = (M + 127) / 128;
        int gy = Nout / 128;
        int gxmax = 148 / gy; if (gxmax < 1) gxmax = 1;
        int gx = ntiles < gxmax ? ntiles : gxmax;
        dim3 grid(gx, gy, 1);
        k_gemm_tc<<<grid, 256, GEMM_SMEM>>>(xh, xl, whi + (size_t)wrow * 128,
                                            wlo + (size_t)wrow * 128, Y, M, Nout,
                                            nullptr, nullptr, nullptr, nullptr, nullptr);
    };
    auto gemm2 = [&](const __nv_bfloat16* xh, const __nv_bfloat16* xl, int wrow, float* Y,
                     const __nv_bfloat16* xh2, const __nv_bfloat16* xl2, int wrow2, float* Y2,
                     int M, int Nout) {
        int ntiles = (M + 127) / 128;
        int gy = Nout / 128;
        int gxmax = 148 / (gy * 2); if (gxmax < 1) gxmax = 1;
        int gx = ntiles < gxmax ? ntiles : gxmax;
        dim3 grid(gx, gy, 2);
        k_gemm_tc<<<grid, 256, GEMM_SMEM>>>(xh, xl, whi + (size_t)wrow * 128,
                                            wlo + (size_t)wrow * 128, Y, M, Nout,
                                            xh2, xl2, whi + (size_t)wrow2 * 128,
                                            wlo + (size_t)wrow2 * 128, Y2);
    };

    // ===== phase 1: CSR build (s1)  ||  wsplit+xsplit+gemm0 (main) =====
    fork(0);
    k_zero_int<<<(NN + 255) / 256, 256, 0, s1>>>(cnt, NN);
    k_hist<<<(EE + 255) / 256, 256, 0, s1>>>(adj_index, cnt);
    k_scan1<<<196, 1024, 0, s1>>>(cnt, rowoff, bsum, NN);
    k_scan2<<<1, 256, 0, s1>>>(bsum, 196);
    k_scan3<<<196, 1024, 0, s1>>>(rowoff, bsum, NN, EE, cursor);
    k_scatter<<<(EE + 255) / 256, 256, 0, s1>>>(adj_index, adj_value, cursor, col, val);
    k_segoff<<<(NN + 255) / 256, 256, 0, s1>>>(ttb, NN, NTTS, ttoff);
    k_segoff<<<(NTTS + 255) / 256, 256, 0, s1>>>(tgb, NTTS, NMOLS, moloff);
    k_vd<<<1, 128, 0, s1>>>(Wsrc, asrc, vsrc);
    k_vd<<<1, 128, 0, s1>>>(Wdst, adst, vdst);

    k_wsplit<<<1024, 256>>>(W_gcn, Wsrc, Wih, Whh, whi, wlo);
    k_xsplit<<<(NN * 32 + 255) / 256, 256>>>(node_attr, xhi, xlo, NN * 32);
    gemm(xhi, xlo, WR_G0, t1, NN, 128);
    join(1);

    // ===== GCN layers =====
    k_spmm<<<NN / 8, 256>>>(t1, nullptr, xhi, xlo, rowoff, col, val, b_gcn,
                            nullptr, nullptr, bg, bb, bm, bv, 0, -1, NN);
    gemm(xhi, xlo, WR_G1, t1, NN, 128);
    k_spmm<<<NN / 8, 256>>>(t1, t2, xhi, xlo, rowoff, col, val, b_gcn + CC,
                            vsrc, ssrc, bg, bb, bm, bv, 1, 2, NN);

    // ===== tt stage: segpool+rowdot (s1)  ||  hs GEMM (main) =====
    fork(2);
    k_segpool<<<(NTTS * 32 + 255) / 256, 256, 0, s1>>>(t2, meanbn_tt, phi, plo, ttoff, NTTS,
                                                       bg, bb, bm, bv, 3);
    k_rowdot<<<(NTTS * 32 + 255) / 256, 256, 0, s1>>>(meanbn_tt, vdst, sdst, NTTS);

    gemm(xhi, xlo, WR_S0, hs, NN, 128);
    join(3);

    k_gat<<<(NTTS * 32 + 255) / 256, 256>>>(hs, ssrc, sdst, ttoff, gbias, ghi, glo, NTTS);
    gemm2(ghi, glo, WR_IH0, gi_tt, phi, plo, WR_HH0, gh_tt, NTTS, 384);
    k_gru<<<(NTTS * CC + 255) / 256, 256>>>(gi_tt, gh_tt, meanbn_tt, bih, bhh,
                                            ttbn, ghi, glo, NTTS, bg, bb, bm, bv, 4, 5);

    // ===== mol stage: segpool+vd+rowdots (s1)  ||  hs2 GEMM (main) =====
    fork(4);
    k_vd<<<1, 128, 0, s1>>>(Wsrc + CC * CC, asrc + CC, vsrc);
    k_vd<<<1, 128, 0, s1>>>(Wdst + CC * CC, adst + CC, vdst);
    k_segpool<<<(NMOLS * 32 + 255) / 256, 256, 0, s1>>>(ttbn, meanbn_mol, phi, plo, moloff,
                                                        NMOLS, bg, bb, bm, bv, 6);
    k_rowdot<<<(NTTS * 32 + 255) / 256, 256, 0, s1>>>(ttbn, vsrc, ssrc, NTTS);
    k_rowdot<<<(NMOLS * 32 + 255) / 256, 256, 0, s1>>>(meanbn_mol, vdst, sdst, NMOLS);

    gemm(ghi, glo, WR_S1, hs2, NTTS, 128);
    join(5);

    k_gat<<<(NMOLS * 32 + 255) / 256, 256>>>(hs2, ssrc, sdst, moloff, gbias + CC,
                                             ghi, glo, NMOLS);
    gemm2(ghi, glo, WR_IH1, gi_mol, phi, plo, WR_HH1, gh_mol, NMOLS, 384);
    k_gru<<<(NMOLS * CC + 255) / 256, 256>>>(gi_mol, gh_mol, meanbn_mol, bih + 3 * CC,
                                             bhh + 3 * CC, molout, nullptr, nullptr,
                                             NMOLS, bg, bb, bm, bv, 7, -1);

    // predictor
    k_pred<<<NMOLS, 64>>>(molout, pW1, pb1, pW2, pb2, outp);
}

// round 15
// speedup vs baseline: 1.1204x; 1.0804x over previous
#include <cuda_runtime.h>
#include <cuda_bf16.h>
#include <mma.h>
#include <stdint.h>
#include <stddef.h>
#include <math.h>

using namespace nvcuda;

#define NN 200000
#define EE 1600000
#define CC 128
#define NTTS 20000
#define NMOLS 2000

// ---------------- static device scratch ----------------
__device__ float g_t1[(size_t)NN * CC];
__device__ float g_t2[(size_t)NN * CC];
__device__ float g_hs[(size_t)NTTS * CC];   // small GEMM output (pre-ELU)
__device__ int   g_cnt[NN];
__device__ int   g_rowoff[NN + 1];
__device__ int   g_cursor[NN];
__device__ int   g_bsum[256];
__device__ int   g_col[EE];
__device__ float g_val[EE];
__device__ int   g_ttoff[NTTS + 1];
__device__ int   g_moloff[NMOLS + 1];
__device__ float g_meanbn_tt[(size_t)NTTS * CC];
__device__ float g_gi_tt[(size_t)NTTS * 3 * CC];
__device__ float g_gh_tt[(size_t)NTTS * 3 * CC];
__device__ float g_ttbn[(size_t)NTTS * CC];
__device__ float g_meanbn_mol[(size_t)NMOLS * CC];
__device__ float g_gi_mol[(size_t)NMOLS * 3 * CC];
__device__ float g_gh_mol[(size_t)NMOLS * 3 * CC];
__device__ float g_molout[(size_t)NMOLS * CC];
__device__ float g_ssrc[NN];
__device__ float g_sdst[NTTS];
__device__ float g_vsrc[CC];
__device__ float g_vdst[CC];
__device__ __nv_bfloat16 g_whi[2048 * 128];
__device__ __nv_bfloat16 g_wlo[2048 * 128];
__device__ __nv_bfloat16 g_xhi[(size_t)NN * CC];
__device__ __nv_bfloat16 g_xlo[(size_t)NN * CC];
__device__ __nv_bfloat16 g_phi[(size_t)NTTS * CC];
__device__ __nv_bfloat16 g_plo[(size_t)NTTS * CC];
__device__ __nv_bfloat16 g_ghi[(size_t)NTTS * CC];
__device__ __nv_bfloat16 g_glo[(size_t)NTTS * CC];
__device__ __nv_bfloat16 g_qhi[(size_t)NTTS * CC];
__device__ __nv_bfloat16 g_qlo[(size_t)NTTS * CC];

#define WR_G0 0
#define WR_G1 128
#define WR_S0 256
#define WR_S1 384
#define WR_IH0 512
#define WR_IH1 896
#define WR_HH0 1280
#define WR_HH1 1664

// ---------------- helpers ----------------
__device__ __forceinline__ uint32_t smem_u32(const void* p) {
    uint32_t a;
    asm("{ .reg .u64 t; cvta.to.shared.u64 t, %1; cvt.u32.u64 %0, t; }" : "=r"(a) : "l"(p));
    return a;
}
__device__ __forceinline__ void cp16(uint32_t saddr, const void* g) {
    asm volatile("cp.async.cg.shared.global [%0], [%1], 16;" :: "r"(saddr), "l"(g));
}
#define CP_COMMIT asm volatile("cp.async.commit_group;" ::: "memory")
#define CP_WAIT(n) asm volatile("cp.async.wait_group %0;" :: "n"(n) : "memory")

__device__ __forceinline__ void write_split(__nv_bfloat16* hi, __nv_bfloat16* lo,
                                            size_t idx, float z) {
    __nv_bfloat16 h = __float2bfloat16(z);
    hi[idx] = h;
    lo[idx] = __float2bfloat16(z - __bfloat162float(h));
}
__device__ __forceinline__ void write_split4(__nv_bfloat16* hi, __nv_bfloat16* lo,
                                             size_t idx0, float z0, float z1,
                                             float z2, float z3) {
    __nv_bfloat162 h01 = __floats2bfloat162_rn(z0, z1);
    __nv_bfloat162 h23 = __floats2bfloat162_rn(z2, z3);
    __nv_bfloat162 l01 = __floats2bfloat162_rn(z0 - __bfloat162float(h01.x),
                                               z1 - __bfloat162float(h01.y));
    __nv_bfloat162 l23 = __floats2bfloat162_rn(z2 - __bfloat162float(h23.x),
                                               z3 - __bfloat162float(h23.y));
    *reinterpret_cast<uint2*>(hi + idx0) =
        make_uint2(*reinterpret_cast<uint32_t*>(&h01), *reinterpret_cast<uint32_t*>(&h23));
    *reinterpret_cast<uint2*>(lo + idx0) =
        make_uint2(*reinterpret_cast<uint32_t*>(&l01), *reinterpret_cast<uint32_t*>(&l23));
}

// ---------------- weight split ----------------
__global__ void k_wsplit(const float* __restrict__ Wg, const float* __restrict__ Ws,
                         const float* __restrict__ Wih, const float* __restrict__ Whh,
                         __nv_bfloat16* __restrict__ hi, __nv_bfloat16* __restrict__ lo) {
    int idx = blockIdx.x * blockDim.x + threadIdx.x;
    int row = idx >> 7, c = idx & 127;
    float w;
    if (row < 256)       w = Wg[(size_t)row * 128 + c];
    else if (row < 512)  w = Ws[(size_t)(row - 256) * 128 + c];
    else if (row < 1280) w = Wih[(size_t)(row - 512) * 128 + c];
    else                 w = Whh[(size_t)(row - 1280) * 128 + c];
    write_split(hi, lo, idx, w);
}

// ---------------- activation split (node_attr) ----------------
__global__ void k_xsplit(const float* __restrict__ X, __nv_bfloat16* __restrict__ hi,
                         __nv_bfloat16* __restrict__ lo, int n4) {
    int i = blockIdx.x * blockDim.x + threadIdx.x;
    if (i >= n4) return;
    float4 x = reinterpret_cast<const float4*>(X)[i];
    write_split4(hi, lo, (size_t)i * 4, x.x, x.y, x.z, x.w);
}

// ---------------- wmma GEMM (R8 config + R14 tail fix) ----------------
#define LDA 136
#define TILE_BYTES (128 * LDA * 2)
#define BH_OFF 0
#define BL_OFF TILE_BYTES
#define A_OFF (2 * TILE_BYTES)
#define GEMM_SMEM (A_OFF + 4 * TILE_BYTES)   // 208,896 B

__global__ __launch_bounds__(256) void k_gemm_tc(
    const __nv_bfloat16* __restrict__ Xhi, const __nv_bfloat16* __restrict__ Xlo,
    const __nv_bfloat16* __restrict__ bhi, const __nv_bfloat16* __restrict__ blo,
    float* __restrict__ Y, int M, int Nout,
    const __nv_bfloat16* __restrict__ X2hi, const __nv_bfloat16* __restrict__ X2lo,
    const __nv_bfloat16* __restrict__ b2hi, const __nv_bfloat16* __restrict__ b2lo,
    float* __restrict__ Y2) {
    extern __shared__ char smem[];
    if (blockIdx.z == 1) {
        Xhi = X2hi; Xlo = X2lo; bhi = b2hi; blo = b2lo; Y = Y2;
    }
    __nv_bfloat16* Bh = reinterpret_cast<__nv_bfloat16*>(smem + BH_OFF);
    __nv_bfloat16* Bl = reinterpret_cast<__nv_bfloat16*>(smem + BL_OFF);

    int tid = threadIdx.x, wid = tid >> 5;
    int tn = blockIdx.y;
    int ntiles = (M + 127) >> 7;
    if ((int)blockIdx.x >= ntiles) return;
    uint32_t sb = smem_u32(smem);

    for (int i = tid; i < 128 * 16; i += 256) {
        int r = i >> 4, c = i & 15;
        cp16(sb + BH_OFF + r * (LDA * 2) + c * 16, &bhi[(size_t)(tn * 128 + r) * 128 + c * 8]);
        cp16(sb + BL_OFF + r * (LDA * 2) + c * 16, &blo[(size_t)(tn * 128 + r) * 128 + c * 8]);
    }
    CP_COMMIT;

    auto load_a = [&](int tm, int st) {
        int row0 = tm * 128;
        uint32_t base = sb + A_OFF + st * 2 * TILE_BYTES;
        for (int i = tid; i < 128 * 16; i += 256) {
            int r = i >> 4, c = i & 15;
            int gr = row0 + r;
            if (gr >= M) gr = M - 1;
            cp16(base + r * (LDA * 2) + c * 16, &Xhi[(size_t)gr * 128 + c * 8]);
            cp16(base + TILE_BYTES + r * (LDA * 2) + c * 16, &Xlo[(size_t)gr * 128 + c * 8]);
        }
        CP_COMMIT;
    };

    load_a(blockIdx.x, 0);

    int wm = wid & 1, wn = wid >> 1;
    int st = 0;
    for (int tm = blockIdx.x; tm < ntiles; tm += gridDim.x, st ^= 1) {
        int tmn = tm + gridDim.x;
        if (tmn < ntiles) {
            load_a(tmn, st ^ 1);
            CP_WAIT(1);
        } else {
            CP_WAIT(0);
        }
        __syncthreads();

        __nv_bfloat16* Ah = reinterpret_cast<__nv_bfloat16*>(smem + A_OFF + st * 2 * TILE_BYTES);
        __nv_bfloat16* Al = Ah + 128 * LDA;

        wmma::fragment<wmma::accumulator, 16, 16, 16, float> cf[4][2];
#pragma unroll
        for (int i = 0; i < 4; i++)
#pragma unroll
            for (int j = 0; j < 2; j++) wmma::fill_fragment(cf[i][j], 0.f);

        const __nv_bfloat16* Aterm[3] = {Ah, Ah, Al};
        const __nv_bfloat16* Bterm[3] = {Bh, Bl, Bh};
#pragma unroll
        for (int t = 0; t < 3; t++) {
            const __nv_bfloat16* As = Aterm[t];
            const __nv_bfloat16* Bs = Bterm[t];
#pragma unroll
            for (int k0 = 0; k0 < 128; k0 += 16) {
                wmma::fragment<wmma::matrix_a, 16, 16, 16, __nv_bfloat16, wmma::row_major> a[4];
                wmma::fragment<wmma::matrix_b, 16, 16, 16, __nv_bfloat16, wmma::col_major> b[2];
#pragma unroll
                for (int i = 0; i < 4; i++)
                    wmma::load_matrix_sync(a[i], &As[(wm * 64 + i * 16) * LDA + k0], LDA);
#pragma unroll
                for (int j = 0; j < 2; j++)
                    wmma::load_matrix_sync(b[j], &Bs[(wn * 32 + j * 16) * LDA + k0], LDA);
#pragma unroll
                for (int i = 0; i < 4; i++)
#pragma unroll
                    for (int j = 0; j < 2; j++) wmma::mma_sync(cf[i][j], a[i], b[j], cf[i][j]);
            }
        }
        int row0 = tm * 128;
#pragma unroll
        for (int i = 0; i < 4; i++) {
            int row = row0 + wm * 64 + i * 16;
            if (row + 16 <= M) {
#pragma unroll
                for (int j = 0; j < 2; j++)
                    wmma::store_matrix_sync(&Y[(size_t)row * Nout + tn * 128 + wn * 32 + j * 16],
                                            cf[i][j], Nout, wmma::mem_row_major);
            }
        }
        __syncthreads();
    }
}

// ---------------- small helpers ----------------
__device__ __forceinline__ float bn_apply(float x, int idx, int ch,
                                          const float* g, const float* b,
                                          const float* m, const float* v) {
    float sc = g[idx * CC + ch] * rsqrtf(v[idx * CC + ch] + 1e-5f);
    return (x - m[idx * CC + ch]) * sc + b[idx * CC + ch];
}
__device__ __forceinline__ float warp_max(float v) {
#pragma unroll
    for (int o = 16; o > 0; o >>= 1) v = fmaxf(v, __shfl_xor_sync(0xffffffffu, v, o));
    return v;
}
__device__ __forceinline__ float warp_sum(float v) {
#pragma unroll
    for (int o = 16; o > 0; o >>= 1) v += __shfl_xor_sync(0xffffffffu, v, o);
    return v;
}

// ---------------- CSR build ----------------
__global__ void k_zero_int(int* p, int n) {
    int i = blockIdx.x * blockDim.x + threadIdx.x;
    if (i < n) p[i] = 0;
}
__global__ void k_hist(const int* __restrict__ idx0, int* __restrict__ cnt) {
    int e = blockIdx.x * blockDim.x + threadIdx.x;
    if (e < EE) atomicAdd(&cnt[idx0[e]], 1);
}
__global__ void k_scan1(const int* __restrict__ in, int* __restrict__ out,
                        int* __restrict__ bsum, int n) {
    __shared__ int sm[1024];
    int i = blockIdx.x * 1024 + threadIdx.x;
    int v = (i < n) ? in[i] : 0;
    sm[threadIdx.x] = v;
    __syncthreads();
    for (int off = 1; off < 1024; off <<= 1) {
        int t = (threadIdx.x >= off) ? sm[threadIdx.x - off] : 0;
        __syncthreads();
        sm[threadIdx.x] += t;
        __syncthreads();
    }
    if (i < n) out[i] = sm[threadIdx.x] - v;
    if (threadIdx.x == 1023) bsum[blockIdx.x] = sm[1023];
}
__global__ void k_scan2(int* __restrict__ bsum, int nb) {
    __shared__ int sm[256];
    int v = (threadIdx.x < nb) ? bsum[threadIdx.x] : 0;
    sm[threadIdx.x] = v;
    __syncthreads();
    for (int off = 1; off < 256; off <<= 1) {
        int t = (threadIdx.x >= off) ? sm[threadIdx.x - off] : 0;
        __syncthreads();
        sm[threadIdx.x] += t;
        __syncthreads();
    }
    if (threadIdx.x < nb) bsum[threadIdx.x] = sm[threadIdx.x] - v;
}
__global__ void k_scan3(int* __restrict__ out, const int* __restrict__ bsum,
                        int n, int total, int* __restrict__ cursor) {
    int i = blockIdx.x * 1024 + threadIdx.x;
    if (i < n) {
        int v = out[i] + bsum[blockIdx.x];
        out[i] = v;
        cursor[i] = v;
    }
    if (i == 0) out[n] = total;
}
__global__ void k_scatter(const int* __restrict__ adj, const float* __restrict__ aval,
                          int* __restrict__ cursor, int* __restrict__ col,
                          float* __restrict__ val) {
    int e = blockIdx.x * blockDim.x + threadIdx.x;
    if (e >= EE) return;
    int r = adj[e];
    int p = atomicAdd(&cursor[r], 1);
    col[p] = adj[EE + e];
    val[p] = aval[e];
}
__global__ void k_segoff(const int* __restrict__ seg, int n, int nseg, int* __restrict__ off) {
    int i = blockIdx.x * blockDim.x + threadIdx.x;
    if (i >= n) return;
    int s = seg[i];
    int p = (i == 0) ? -1 : seg[i - 1];
    for (int t = p + 1; t <= s; ++t) off[t] = i;
    if (i == n - 1)
        for (int t = s + 1; t <= nseg; ++t) off[t] = n;
}

// ---------------- SpMM (strided lanes, 4-edge unroll) + bias + BN(+relu)(+BN2) ----------------
__global__ void k_spmm(const float* __restrict__ Xin, float* __restrict__ Yf,
                       __nv_bfloat16* __restrict__ Yhi, __nv_bfloat16* __restrict__ Ylo,
                       const int* __restrict__ rowoff, const int* __restrict__ col,
                       const float* __restrict__ val, const float* __restrict__ bias,
                       const float* __restrict__ vsrc, float* __restrict__ svout,
                       const float* __restrict__ bg, const float* __restrict__ bb,
                       const float* __restrict__ bm, const float* __restrict__ bv,
                       int bnA, int bnB, int M) {
    int gw = (blockIdx.x * blockDim.x + threadIdx.x) >> 5;
    int lane = threadIdx.x & 31;
    if (gw >= M) return;
    int s = rowoff[gw], e = rowoff[gw + 1];
    float acc[4] = {0.f, 0.f, 0.f, 0.f};
    int i = s;
    for (; i + 3 < e; i += 4) {
        int c0 = col[i], c1 = col[i + 1], c2 = col[i + 2], c3 = col[i + 3];
        float v0 = val[i], v1 = val[i + 1], v2 = val[i + 2], v3 = val[i + 3];
        const float* x0 = Xin + (size_t)c0 * CC;
        const float* x1 = Xin + (size_t)c1 * CC;
        const float* x2 = Xin + (size_t)c2 * CC;
        const float* x3 = Xin + (size_t)c3 * CC;
#pragma unroll
        for (int j = 0; j < 4; j++)
            acc[j] += v0 * x0[lane + 32 * j] + v1 * x1[lane + 32 * j] +
                      v2 * x2[lane + 32 * j] + v3 * x3[lane + 32 * j];
    }
    for (; i < e; i++) {
        int c0 = col[i];
        float v0 = val[i];
        const float* x0 = Xin + (size_t)c0 * CC;
#pragma unroll
        for (int j = 0; j < 4; j++) acc[j] += v0 * x0[lane + 32 * j];
    }
    float sdot = 0.f;
#pragma unroll
    for (int j = 0; j < 4; j++) {
        int ch = lane + 32 * j;
        float z = acc[j] + bias[ch];
        z = bn_apply(z, bnA, ch, bg, bb, bm, bv);
        z = fmaxf(z, 0.f);
        if (bnB >= 0) z = bn_apply(z, bnB, ch, bg, bb, bm, bv);
        size_t idx = (size_t)gw * CC + ch;
        if (Yf) Yf[idx] = z;
        if (Yhi) write_split(Yhi, Ylo, idx, z);
        if (vsrc) sdot += z * vsrc[ch];
    }
    if (vsrc) {
        sdot = warp_sum(sdot);
        if (lane == 0) svout[gw] = sdot;
    }
}

// ---------------- segment sum pool + relu + BN; f32 + bf16-split out ----------------
__global__ void k_segpool(const float* __restrict__ X, float* __restrict__ Yf,
                          __nv_bfloat16* __restrict__ Yhi, __nv_bfloat16* __restrict__ Ylo,
                          const int* __restrict__ off, int nseg,
                          const float* bg, const float* bb, const float* bm,
                          const float* bv, int bi) {
    int gw = (blockIdx.x * blockDim.x + threadIdx.x) >> 5;
    int lane = threadIdx.x & 31;
    if (gw >= nseg) return;
    int s = off[gw], e = off[gw + 1];
    float acc[4] = {0.f, 0.f, 0.f, 0.f};
    for (int i = s; i < e; i++) {
        const float* xr = X + (size_t)i * CC;
#pragma unroll
        for (int j = 0; j < 4; j++) acc[j] += xr[lane + 32 * j];
    }
#pragma unroll
    for (int j = 0; j < 4; j++) {
        int ch = lane + 32 * j;
        float z = bn_apply(fmaxf(acc[j], 0.f), bi, ch, bg, bb, bm, bv);
        size_t idx = (size_t)gw * CC + ch;
        Yf[idx] = z;
        write_split(Yhi, Ylo, idx, z);
    }
}

// vd[c] = sum_o ad[o] * Wd[o,c]
__global__ void k_vd(const float* __restrict__ Wd, const float* __restrict__ ad,
                     float* __restrict__ vd) {
    int c = threadIdx.x;
    float s = 0.f;
    for (int o = 0; o < CC; o++) s += ad[o] * Wd[o * CC + c];
    vd[c] = s;
}
__global__ void k_rowdot(const float* __restrict__ X, const float* __restrict__ v,
                         float* __restrict__ out, int M) {
    int gw = (blockIdx.x * blockDim.x + threadIdx.x) >> 5;
    int lane = threadIdx.x & 31;
    if (gw >= M) return;
    const float* xr = X + (size_t)gw * CC;
    float s = 0.f;
#pragma unroll
    for (int j = 0; j < 4; j++) s += xr[lane + 32 * j] * v[lane + 32 * j];
    s = warp_sum(s);
    if (lane == 0) out[gw] = s;
}

// ---------------- GAT softmax + weighted aggregate over SRC FEATURES -> bf16-split q ----------------
__global__ void k_gat(const float* __restrict__ X, const float* __restrict__ ssrc,
                      const float* __restrict__ sdst, const int* __restrict__ off,
                      __nv_bfloat16* __restrict__ outhi, __nv_bfloat16* __restrict__ outlo,
                      int nseg) {
    int gw = (blockIdx.x * blockDim.x + threadIdx.x) >> 5;
    int lane = threadIdx.x & 31;
    if (gw >= nseg) return;
    int s = off[gw], e = off[gw + 1];
    float sd = sdst[gw];
    float acc[4] = {0.f, 0.f, 0.f, 0.f};
    if (e > s) {
        float mx = -3.402823e38f;
        for (int i = s + lane; i < e; i += 32) {
            float a = ssrc[i] + sd;
            a = a > 0.f ? a : 0.01f * a;
            mx = fmaxf(mx, a);
        }
        mx = warp_max(mx);
        float den = 0.f;
        for (int i = s + lane; i < e; i += 32) {
            float a = ssrc[i] + sd;
            a = a > 0.f ? a : 0.01f * a;
            den += __expf(a - mx);
        }
        den = warp_sum(den);
        float inv = 1.f / den;
        for (int i = s; i < e; i++) {
            float a = ssrc[i] + sd;
            a = a > 0.f ? a : 0.01f * a;
            float w = __expf(a - mx) * inv;
            const float* hr = X + (size_t)i * CC;
#pragma unroll
            for (int j = 0; j < 4; j++) acc[j] += w * hr[lane + 32 * j];
        }
    }
#pragma unroll
    for (int j = 0; j < 4; j++)
        write_split(outhi, outlo, (size_t)gw * CC + lane + 32 * j, acc[j]);
}

// ---------------- bias + ELU + split (post small GEMM) ----------------
__global__ void k_elu(const float* __restrict__ X, const float* __restrict__ bias,
                      __nv_bfloat16* __restrict__ outhi, __nv_bfloat16* __restrict__ outlo,
                      int n) {
    int idx = blockIdx.x * blockDim.x + threadIdx.x;
    if (idx >= n) return;
    int c = idx & 127;
    float v = X[idx] + bias[c];
    v = v > 0.f ? v : (__expf(v) - 1.f);
    write_split(outhi, outlo, idx, v);
}

// ---------------- GRU gates (+ folded biases) + relu + BN(+BN2) ----------------
__global__ void k_gru(const float* __restrict__ gi, const float* __restrict__ gh,
                      const float* __restrict__ h, const float* __restrict__ bih,
                      const float* __restrict__ bhh, float* __restrict__ outf,
                      __nv_bfloat16* __restrict__ outhi, __nv_bfloat16* __restrict__ outlo,
                      int M, const float* bg, const float* bb, const float* bm,
                      const float* bv, int bnA, int bnB) {
    int idx = blockIdx.x * blockDim.x + threadIdx.x;
    if (idx >= M * CC) return;
    int t = idx >> 7, c = idx & 127;
    const float* gir = gi + (size_t)t * 3 * CC;
    const float* ghr = gh + (size_t)t * 3 * CC;
    float r = 1.f / (1.f + __expf(-(gir[c] + bih[c] + ghr[c] + bhh[c])));
    float z = 1.f / (1.f + __expf(-(gir[CC + c] + bih[CC + c] + ghr[CC + c] + bhh[CC + c])));
    float n = tanhf(gir[2 * CC + c] + bih[2 * CC + c] +
                    r * (ghr[2 * CC + c] + bhh[2 * CC + c]));
    float hv = (1.f - z) * n + z * h[idx];
    float y = fmaxf(hv, 0.f);
    y = bn_apply(y, bnA, c, bg, bb, bm, bv);
    if (bnB >= 0) y = bn_apply(y, bnB, c, bg, bb, bm, bv);
    outf[idx] = y;
    if (outhi) write_split(outhi, outlo, idx, y);
}

// ---------------- predictor ----------------
__global__ void k_pred(const float* __restrict__ mol, const float* __restrict__ W1,
                       const float* __restrict__ b1, const float* __restrict__ W2,
                       const float* __restrict__ b2, float* __restrict__ out) {
    __shared__ float xr[CC];
    __shared__ float hr[64];
    int m = blockIdx.x, t = threadIdx.x;
    xr[t] = mol[(size_t)m * CC + t];
    xr[t + 64] = mol[(size_t)m * CC + t + 64];
    __syncthreads();
    float s = b1[t];
    for (int c = 0; c < CC; c++) s += W1[t * CC + c] * xr[c];
    s = fmaxf(s, 0.f);
    hr[t] = s * W2[t];
    __syncthreads();
    for (int off = 32; off > 0; off >>= 1) {
        if (t < off) hr[t] += hr[t + off];
        __syncthreads();
    }
    if (t == 0) out[m] = hr[0] + b2[0];
}

// ---------------- host ----------------
extern "C" void kernel_launch(void* const* d_in, const int* in_sizes, int n_in,
                              void* d_out, int out_size) {
    if (n_in < 24) return;
    const float *node_attr, *adj_value, *W_gcn, *b_gcn, *bg, *bb, *bm, *bv;
    const float *Wsrc, *Wdst, *asrc, *adst, *gbias, *Wih, *Whh, *bih, *bhh;
    const float *pW1, *pb1, *pW2, *pb2;
    const int *adj_index, *ttb, *tgb;
    if (in_sizes[1] == EE) {
        node_attr = (const float*)d_in[0];  adj_value = (const float*)d_in[1];
        W_gcn = (const float*)d_in[2];      b_gcn = (const float*)d_in[3];
        bg = (const float*)d_in[4];         bb = (const float*)d_in[5];
        bm = (const float*)d_in[6];         bv = (const float*)d_in[7];
        Wsrc = (const float*)d_in[8];       Wdst = (const float*)d_in[9];
        asrc = (const float*)d_in[10];      adst = (const float*)d_in[11];
        gbias = (const float*)d_in[12];     Wih = (const float*)d_in[13];
        Whh = (const float*)d_in[14];       bih = (const float*)d_in[15];
        bhh = (const float*)d_in[16];       pW1 = (const float*)d_in[17];
        pb1 = (const float*)d_in[18];       pW2 = (const float*)d_in[19];
        pb2 = (const float*)d_in[20];       adj_index = (const int*)d_in[21];
        ttb = (const int*)d_in[22];         tgb = (const int*)d_in[23];
    } else {
        node_attr = (const float*)d_in[0];  adj_index = (const int*)d_in[1];
        adj_value = (const float*)d_in[2];  ttb = (const int*)d_in[3];
        tgb = (const int*)d_in[4];          W_gcn = (const float*)d_in[5];
        b_gcn = (const float*)d_in[6];      bg = (const float*)d_in[7];
        bb = (const float*)d_in[8];         bm = (const float*)d_in[9];
        bv = (const float*)d_in[10];        Wsrc = (const float*)d_in[11];
        Wdst = (const float*)d_in[12];      asrc = (const float*)d_in[13];
        adst = (const float*)d_in[14];      gbias = (const float*)d_in[15];
        Wih = (const float*)d_in[16];       Whh = (const float*)d_in[17];
        bih = (const float*)d_in[18];       bhh = (const float*)d_in[19];
        pW1 = (const float*)d_in[20];       pb1 = (const float*)d_in[21];
        pW2 = (const float*)d_in[22];       pb2 = (const float*)d_in[23];
    }

    void* p;
    cudaGetSymbolAddress(&p, g_t1);        float* t1 = (float*)p;
    cudaGetSymbolAddress(&p, g_t2);        float* t2 = (float*)p;
    cudaGetSymbolAddress(&p, g_hs);        float* hsTmp = (float*)p;
    cudaGetSymbolAddress(&p, g_cnt);       int* cnt = (int*)p;
    cudaGetSymbolAddress(&p, g_rowoff);    int* rowoff = (int*)p;
    cudaGetSymbolAddress(&p, g_cursor);    int* cursor = (int*)p;
    cudaGetSymbolAddress(&p, g_bsum);      int* bsum = (int*)p;
    cudaGetSymbolAddress(&p, g_col);       int* col = (int*)p;
    cudaGetSymbolAddress(&p, g_val);       float* val = (float*)p;
    cudaGetSymbolAddress(&p, g_ttoff);     int* ttoff = (int*)p;
    cudaGetSymbolAddress(&p, g_moloff);    int* moloff = (int*)p;
    cudaGetSymbolAddress(&p, g_meanbn_tt); float* meanbn_tt = (float*)p;
    cudaGetSymbolAddress(&p, g_gi_tt);     float* gi_tt = (float*)p;
    cudaGetSymbolAddress(&p, g_gh_tt);     float* gh_tt = (float*)p;
    cudaGetSymbolAddress(&p, g_ttbn);      float* ttbn = (float*)p;
    cudaGetSymbolAddress(&p, g_meanbn_mol);float* meanbn_mol = (float*)p;
    cudaGetSymbolAddress(&p, g_gi_mol);    float* gi_mol = (float*)p;
    cudaGetSymbolAddress(&p, g_gh_mol);    float* gh_mol = (float*)p;
    cudaGetSymbolAddress(&p, g_molout);    float* molout = (float*)p;
    cudaGetSymbolAddress(&p, g_ssrc);      float* ssrc = (float*)p;
    cudaGetSymbolAddress(&p, g_sdst);      float* sdst = (float*)p;
    cudaGetSymbolAddress(&p, g_vsrc);      float* vsrc = (float*)p;
    cudaGetSymbolAddress(&p, g_vdst);      float* vdst = (float*)p;
    cudaGetSymbolAddress(&p, g_whi);       __nv_bfloat16* whi = (__nv_bfloat16*)p;
    cudaGetSymbolAddress(&p, g_wlo);       __nv_bfloat16* wlo = (__nv_bfloat16*)p;
    cudaGetSymbolAddress(&p, g_xhi);       __nv_bfloat16* xhi = (__nv_bfloat16*)p;
    cudaGetSymbolAddress(&p, g_xlo);       __nv_bfloat16* xlo = (__nv_bfloat16*)p;
    cudaGetSymbolAddress(&p, g_phi);       __nv_bfloat16* phi = (__nv_bfloat16*)p;
    cudaGetSymbolAddress(&p, g_plo);       __nv_bfloat16* plo = (__nv_bfloat16*)p;
    cudaGetSymbolAddress(&p, g_ghi);       __nv_bfloat16* ghi = (__nv_bfloat16*)p;
    cudaGetSymbolAddress(&p, g_glo);       __nv_bfloat16* glo = (__nv_bfloat16*)p;
    cudaGetSymbolAddress(&p, g_qhi);       __nv_bfloat16* qhi = (__nv_bfloat16*)p;
    cudaGetSymbolAddress(&p, g_qlo);       __nv_bfloat16* qlo = (__nv_bfloat16*)p;
    float* outp = (float*)d_out;

    static cudaStream_t s1 = nullptr;
    static cudaEvent_t ev[8];
    if (s1 == nullptr) {
        cudaStreamCreateWithFlags(&s1, cudaStreamNonBlocking);
        for (int i = 0; i < 8; i++) cudaEventCreateWithFlags(&ev[i], cudaEventDisableTiming);
    }
    auto fork = [&](int i) {
        cudaEventRecord(ev[i], 0);
        cudaStreamWaitEvent(s1, ev[i], 0);
    };
    auto join = [&](int i) {
        cudaEventRecord(ev[i], s1);
        cudaStreamWaitEvent((cudaStream_t)0, ev[i], 0);
    };

    cudaFuncSetAttribute(k_gemm_tc, cudaFuncAttributeMaxDynamicSharedMemorySize, GEMM_SMEM);

    auto gemm = [&](const __nv_bfloat16* xh, const __nv_bfloat16* xl, int wrow,
                    float* Y, int M, int Nout) {
        int ntiles = (M + 127) / 128;
        int gy = Nout / 128;
        int gxmax = 148 / gy; if (gxmax < 1) gxmax = 1;
        int gx = ntiles < gxmax ? ntiles : gxmax;
        dim3 grid(gx, gy, 1);
        k_gemm_tc<<<grid, 256, GEMM_SMEM>>>(xh, xl, whi + (size_t)wrow * 128,
                                            wlo + (size_t)wrow * 128, Y, M, Nout,
                                            nullptr, nullptr, nullptr, nullptr, nullptr);
    };
    auto gemm2 = [&](const __nv_bfloat16* xh, const __nv_bfloat16* xl, int wrow, float* Y,
                     const __nv_bfloat16* xh2, const __nv_bfloat16* xl2, int wrow2, float* Y2,
                     int M, int Nout) {
        int ntiles = (M + 127) / 128;
        int gy = Nout / 128;
        int gxmax = 148 / (gy * 2); if (gxmax < 1) gxmax = 1;
        int gx = ntiles < gxmax ? ntiles : gxmax;
        dim3 grid(gx, gy, 2);
        k_gemm_tc<<<grid, 256, GEMM_SMEM>>>(xh, xl, whi + (size_t)wrow * 128,
                                            wlo + (size_t)wrow * 128, Y, M, Nout,
                                            xh2, xl2, whi + (size_t)wrow2 * 128,
                                            wlo + (size_t)wrow2 * 128, Y2);
    };

    // ===== phase 1: CSR build (s1)  ||  wsplit+xsplit+gemm0 (main) =====
    fork(0);
    k_zero_int<<<(NN + 255) / 256, 256, 0, s1>>>(cnt, NN);
    k_hist<<<(EE + 255) / 256, 256, 0, s1>>>(adj_index, cnt);
    k_scan1<<<196, 1024, 0, s1>>>(cnt, rowoff, bsum, NN);
    k_scan2<<<1, 256, 0, s1>>>(bsum, 196);
    k_scan3<<<196, 1024, 0, s1>>>(rowoff, bsum, NN, EE, cursor);
    k_scatter<<<(EE + 255) / 256, 256, 0, s1>>>(adj_index, adj_value, cursor, col, val);
    k_segoff<<<(NN + 255) / 256, 256, 0, s1>>>(ttb, NN, NTTS, ttoff);
    k_segoff<<<(NTTS + 255) / 256, 256, 0, s1>>>(tgb, NTTS, NMOLS, moloff);
    k_vd<<<1, 128, 0, s1>>>(Wsrc, asrc, vsrc);
    k_vd<<<1, 128, 0, s1>>>(Wdst, adst, vdst);

    k_wsplit<<<1024, 256>>>(W_gcn, Wsrc, Wih, Whh, whi, wlo);
    k_xsplit<<<(NN * 32 + 255) / 256, 256>>>(node_attr, xhi, xlo, NN * 32);
    gemm(xhi, xlo, WR_G0, t1, NN, 128);
    join(1);

    // ===== GCN layers =====
    k_spmm<<<NN / 8, 256>>>(t1, nullptr, xhi, xlo, rowoff, col, val, b_gcn,
                            nullptr, nullptr, bg, bb, bm, bv, 0, -1, NN);
    gemm(xhi, xlo, WR_G1, t1, NN, 128);
    // spmm2: t2 f32 only (no split needed now) + fused ssrc rowdot
    k_spmm<<<NN / 8, 256>>>(t1, t2, nullptr, nullptr, rowoff, col, val, b_gcn + CC,
                            vsrc, ssrc, bg, bb, bm, bv, 1, 2, NN);

    // ===== tt stage: pooled-GAT trick (gat aggregates x2, then small GEMM) =====
    k_segpool<<<(NTTS * 32 + 255) / 256, 256>>>(t2, meanbn_tt, phi, plo, ttoff, NTTS,
                                                bg, bb, bm, bv, 3);
    k_rowdot<<<(NTTS * 32 + 255) / 256, 256>>>(meanbn_tt, vdst, sdst, NTTS);
    k_gat<<<(NTTS * 32 + 255) / 256, 256>>>(t2, ssrc, sdst, ttoff, qhi, qlo, NTTS);
    gemm(qhi, qlo, WR_S0, hsTmp, NTTS, 128);
    k_elu<<<(NTTS * CC + 255) / 256, 256>>>(hsTmp, gbias, ghi, glo, NTTS * CC);
    gemm2(ghi, glo, WR_IH0, gi_tt, phi, plo, WR_HH0, gh_tt, NTTS, 384);
    k_gru<<<(NTTS * CC + 255) / 256, 256>>>(gi_tt, gh_tt, meanbn_tt, bih, bhh,
                                            ttbn, ghi, glo, NTTS, bg, bb, bm, bv, 4, 5);

    // ===== mol stage =====
    fork(4);
    k_vd<<<1, 128, 0, s1>>>(Wsrc + CC * CC, asrc + CC, vsrc);
    k_vd<<<1, 128, 0, s1>>>(Wdst + CC * CC, adst + CC, vdst);
    k_rowdot<<<(NTTS * 32 + 255) / 256, 256, 0, s1>>>(ttbn, vsrc, ssrc, NTTS);

    k_segpool<<<(NMOLS * 32 + 255) / 256, 256>>>(ttbn, meanbn_mol, phi, plo, moloff,
                                                 NMOLS, bg, bb, bm, bv, 6);
    join(5);
    k_rowdot<<<(NMOLS * 32 + 255) / 256, 256>>>(meanbn_mol, vdst, sdst, NMOLS);
    k_gat<<<(NMOLS * 32 + 255) / 256, 256>>>(ttbn, ssrc, sdst, moloff, qhi, qlo, NMOLS);
    gemm(qhi, qlo, WR_S1, hsTmp, NMOLS, 128);
    k_elu<<<(NMOLS * CC + 255) / 256, 256>>>(hsTmp, gbias + CC, ghi, glo, NMOLS * CC);
    gemm2(ghi, glo, WR_IH1, gi_mol, phi, plo, WR_HH1, gh_mol, NMOLS, 384);
    k_gru<<<(NMOLS * CC + 255) / 256, 256>>>(gi_mol, gh_mol, meanbn_mol, bih + 3 * CC,
                                             bhh + 3 * CC, molout, nullptr, nullptr,
                                             NMOLS, bg, bb, bm, bv, 7, -1);

    // predictor
    k_pred<<<NMOLS, 64>>>(molout, pW1, pb1, pW2, pb2, outp);
}

// round 16
// speedup vs baseline: 1.1449x; 1.0219x over previous
#include <cuda_runtime.h>
#include <cuda_bf16.h>
#include <mma.h>
#include <stdint.h>
#include <stddef.h>
#include <math.h>

using namespace nvcuda;

#define NN 200000
#define EE 1600000
#define CC 128
#define NTTS 20000
#define NMOLS 2000

// ---------------- static device scratch ----------------
__device__ float g_t1[(size_t)NN * CC];
__device__ float g_t2[(size_t)NN * CC];
__device__ float g_hs[(size_t)NTTS * CC];   // small GEMM output (pre-ELU)
__device__ int   g_cnt[NN];
__device__ int   g_rowoff[NN + 1];
__device__ int   g_cursor[NN];
__device__ int   g_bsum[256];
__device__ int   g_col[EE];
__device__ float g_val[EE];
__device__ int   g_ttoff[NTTS + 1];
__device__ int   g_moloff[NMOLS + 1];
__device__ float g_meanbn_tt[(size_t)NTTS * CC];
__device__ float g_gi_tt[(size_t)NTTS * 3 * CC];
__device__ float g_gh_tt[(size_t)NTTS * 3 * CC];
__device__ float g_ttbn[(size_t)NTTS * CC];
__device__ float g_meanbn_mol[(size_t)NMOLS * CC];
__device__ float g_gi_mol[(size_t)NMOLS * 3 * CC];
__device__ float g_gh_mol[(size_t)NMOLS * 3 * CC];
__device__ float g_molout[(size_t)NMOLS * CC];
__device__ float g_ssrc[NN];
__device__ float g_vsrc[CC];
__device__ float g_vdst[CC];
__device__ __nv_bfloat16 g_whi[2048 * 128];
__device__ __nv_bfloat16 g_wlo[2048 * 128];
__device__ __nv_bfloat16 g_xhi[(size_t)NN * CC];
__device__ __nv_bfloat16 g_xlo[(size_t)NN * CC];
__device__ __nv_bfloat16 g_phi[(size_t)NTTS * CC];
__device__ __nv_bfloat16 g_plo[(size_t)NTTS * CC];
__device__ __nv_bfloat16 g_ghi[(size_t)NTTS * CC];
__device__ __nv_bfloat16 g_glo[(size_t)NTTS * CC];
__device__ __nv_bfloat16 g_qhi[(size_t)NTTS * CC];
__device__ __nv_bfloat16 g_qlo[(size_t)NTTS * CC];

#define WR_G0 0
#define WR_G1 128
#define WR_S0 256
#define WR_S1 384
#define WR_IH0 512
#define WR_IH1 896
#define WR_HH0 1280
#define WR_HH1 1664

// ---------------- helpers ----------------
__device__ __forceinline__ uint32_t smem_u32(const void* p) {
    uint32_t a;
    asm("{ .reg .u64 t; cvta.to.shared.u64 t, %1; cvt.u32.u64 %0, t; }" : "=r"(a) : "l"(p));
    return a;
}
__device__ __forceinline__ void cp16(uint32_t saddr, const void* g) {
    asm volatile("cp.async.cg.shared.global [%0], [%1], 16;" :: "r"(saddr), "l"(g));
}
#define CP_COMMIT asm volatile("cp.async.commit_group;" ::: "memory")
#define CP_WAIT(n) asm volatile("cp.async.wait_group %0;" :: "n"(n) : "memory")

__device__ __forceinline__ void write_split(__nv_bfloat16* hi, __nv_bfloat16* lo,
                                            size_t idx, float z) {
    __nv_bfloat16 h = __float2bfloat16(z);
    hi[idx] = h;
    lo[idx] = __float2bfloat16(z - __bfloat162float(h));
}
__device__ __forceinline__ void write_split4(__nv_bfloat16* hi, __nv_bfloat16* lo,
                                             size_t idx0, float z0, float z1,
                                             float z2, float z3) {
    __nv_bfloat162 h01 = __floats2bfloat162_rn(z0, z1);
    __nv_bfloat162 h23 = __floats2bfloat162_rn(z2, z3);
    __nv_bfloat162 l01 = __floats2bfloat162_rn(z0 - __bfloat162float(h01.x),
                                               z1 - __bfloat162float(h01.y));
    __nv_bfloat162 l23 = __floats2bfloat162_rn(z2 - __bfloat162float(h23.x),
                                               z3 - __bfloat162float(h23.y));
    *reinterpret_cast<uint2*>(hi + idx0) =
        make_uint2(*reinterpret_cast<uint32_t*>(&h01), *reinterpret_cast<uint32_t*>(&h23));
    *reinterpret_cast<uint2*>(lo + idx0) =
        make_uint2(*reinterpret_cast<uint32_t*>(&l01), *reinterpret_cast<uint32_t*>(&l23));
}

// ---------------- weight split ----------------
__global__ void k_wsplit(const float* __restrict__ Wg, const float* __restrict__ Ws,
                         const float* __restrict__ Wih, const float* __restrict__ Whh,
                         __nv_bfloat16* __restrict__ hi, __nv_bfloat16* __restrict__ lo) {
    int idx = blockIdx.x * blockDim.x + threadIdx.x;
    int row = idx >> 7, c = idx & 127;
    float w;
    if (row < 256)       w = Wg[(size_t)row * 128 + c];
    else if (row < 512)  w = Ws[(size_t)(row - 256) * 128 + c];
    else if (row < 1280) w = Wih[(size_t)(row - 512) * 128 + c];
    else                 w = Whh[(size_t)(row - 1280) * 128 + c];
    write_split(hi, lo, idx, w);
}

// ---------------- activation split (node_attr) ----------------
__global__ void k_xsplit(const float* __restrict__ X, __nv_bfloat16* __restrict__ hi,
                         __nv_bfloat16* __restrict__ lo, int n4) {
    int i = blockIdx.x * blockDim.x + threadIdx.x;
    if (i >= n4) return;
    float4 x = reinterpret_cast<const float4*>(X)[i];
    write_split4(hi, lo, (size_t)i * 4, x.x, x.y, x.z, x.w);
}

// ---------------- wmma GEMM (R8 config + R14 tail fix) ----------------
#define LDA 136
#define TILE_BYTES (128 * LDA * 2)
#define BH_OFF 0
#define BL_OFF TILE_BYTES
#define A_OFF (2 * TILE_BYTES)
#define GEMM_SMEM (A_OFF + 4 * TILE_BYTES)   // 208,896 B

__global__ __launch_bounds__(256) void k_gemm_tc(
    const __nv_bfloat16* __restrict__ Xhi, const __nv_bfloat16* __restrict__ Xlo,
    const __nv_bfloat16* __restrict__ bhi, const __nv_bfloat16* __restrict__ blo,
    float* __restrict__ Y, int M, int Nout,
    const __nv_bfloat16* __restrict__ X2hi, const __nv_bfloat16* __restrict__ X2lo,
    const __nv_bfloat16* __restrict__ b2hi, const __nv_bfloat16* __restrict__ b2lo,
    float* __restrict__ Y2) {
    extern __shared__ char smem[];
    if (blockIdx.z == 1) {
        Xhi = X2hi; Xlo = X2lo; bhi = b2hi; blo = b2lo; Y = Y2;
    }
    __nv_bfloat16* Bh = reinterpret_cast<__nv_bfloat16*>(smem + BH_OFF);
    __nv_bfloat16* Bl = reinterpret_cast<__nv_bfloat16*>(smem + BL_OFF);

    int tid = threadIdx.x, wid = tid >> 5;
    int tn = blockIdx.y;
    int ntiles = (M + 127) >> 7;
    if ((int)blockIdx.x >= ntiles) return;
    uint32_t sb = smem_u32(smem);

    for (int i = tid; i < 128 * 16; i += 256) {
        int r = i >> 4, c = i & 15;
        cp16(sb + BH_OFF + r * (LDA * 2) + c * 16, &bhi[(size_t)(tn * 128 + r) * 128 + c * 8]);
        cp16(sb + BL_OFF + r * (LDA * 2) + c * 16, &blo[(size_t)(tn * 128 + r) * 128 + c * 8]);
    }
    CP_COMMIT;

    auto load_a = [&](int tm, int st) {
        int row0 = tm * 128;
        uint32_t base = sb + A_OFF + st * 2 * TILE_BYTES;
        for (int i = tid; i < 128 * 16; i += 256) {
            int r = i >> 4, c = i & 15;
            int gr = row0 + r;
            if (gr >= M) gr = M - 1;
            cp16(base + r * (LDA * 2) + c * 16, &Xhi[(size_t)gr * 128 + c * 8]);
            cp16(base + TILE_BYTES + r * (LDA * 2) + c * 16, &Xlo[(size_t)gr * 128 + c * 8]);
        }
        CP_COMMIT;
    };

    load_a(blockIdx.x, 0);

    int wm = wid & 1, wn = wid >> 1;
    int st = 0;
    for (int tm = blockIdx.x; tm < ntiles; tm += gridDim.x, st ^= 1) {
        int tmn = tm + gridDim.x;
        if (tmn < ntiles) {
            load_a(tmn, st ^ 1);
            CP_WAIT(1);
        } else {
            CP_WAIT(0);
        }
        __syncthreads();

        __nv_bfloat16* Ah = reinterpret_cast<__nv_bfloat16*>(smem + A_OFF + st * 2 * TILE_BYTES);
        __nv_bfloat16* Al = Ah + 128 * LDA;

        wmma::fragment<wmma::accumulator, 16, 16, 16, float> cf[4][2];
#pragma unroll
        for (int i = 0; i < 4; i++)
#pragma unroll
            for (int j = 0; j < 2; j++) wmma::fill_fragment(cf[i][j], 0.f);

        const __nv_bfloat16* Aterm[3] = {Ah, Ah, Al};
        const __nv_bfloat16* Bterm[3] = {Bh, Bl, Bh};
#pragma unroll
        for (int t = 0; t < 3; t++) {
            const __nv_bfloat16* As = Aterm[t];
            const __nv_bfloat16* Bs = Bterm[t];
#pragma unroll
            for (int k0 = 0; k0 < 128; k0 += 16) {
                wmma::fragment<wmma::matrix_a, 16, 16, 16, __nv_bfloat16, wmma::row_major> a[4];
                wmma::fragment<wmma::matrix_b, 16, 16, 16, __nv_bfloat16, wmma::col_major> b[2];
#pragma unroll
                for (int i = 0; i < 4; i++)
                    wmma::load_matrix_sync(a[i], &As[(wm * 64 + i * 16) * LDA + k0], LDA);
#pragma unroll
                for (int j = 0; j < 2; j++)
                    wmma::load_matrix_sync(b[j], &Bs[(wn * 32 + j * 16) * LDA + k0], LDA);
#pragma unroll
                for (int i = 0; i < 4; i++)
#pragma unroll
                    for (int j = 0; j < 2; j++) wmma::mma_sync(cf[i][j], a[i], b[j], cf[i][j]);
            }
        }
        int row0 = tm * 128;
#pragma unroll
        for (int i = 0; i < 4; i++) {
            int row = row0 + wm * 64 + i * 16;
            if (row + 16 <= M) {
#pragma unroll
                for (int j = 0; j < 2; j++)
                    wmma::store_matrix_sync(&Y[(size_t)row * Nout + tn * 128 + wn * 32 + j * 16],
                                            cf[i][j], Nout, wmma::mem_row_major);
            }
        }
        __syncthreads();
    }
}

// ---------------- small helpers ----------------
__device__ __forceinline__ float bn_apply(float x, int idx, int ch,
                                          const float* g, const float* b,
                                          const float* m, const float* v) {
    float sc = g[idx * CC + ch] * rsqrtf(v[idx * CC + ch] + 1e-5f);
    return (x - m[idx * CC + ch]) * sc + b[idx * CC + ch];
}
__device__ __forceinline__ float warp_max(float v) {
#pragma unroll
    for (int o = 16; o > 0; o >>= 1) v = fmaxf(v, __shfl_xor_sync(0xffffffffu, v, o));
    return v;
}
__device__ __forceinline__ float warp_sum(float v) {
#pragma unroll
    for (int o = 16; o > 0; o >>= 1) v += __shfl_xor_sync(0xffffffffu, v, o);
    return v;
}

// ---------------- CSR build ----------------
__global__ void k_zero_int(int* p, int n) {
    int i = blockIdx.x * blockDim.x + threadIdx.x;
    if (i < n) p[i] = 0;
}
__global__ void k_hist(const int* __restrict__ idx0, int* __restrict__ cnt) {
    int e = blockIdx.x * blockDim.x + threadIdx.x;
    if (e < EE) atomicAdd(&cnt[idx0[e]], 1);
}
__global__ void k_scan1(const int* __restrict__ in, int* __restrict__ out,
                        int* __restrict__ bsum, int n) {
    __shared__ int sm[1024];
    int i = blockIdx.x * 1024 + threadIdx.x;
    int v = (i < n) ? in[i] : 0;
    sm[threadIdx.x] = v;
    __syncthreads();
    for (int off = 1; off < 1024; off <<= 1) {
        int t = (threadIdx.x >= off) ? sm[threadIdx.x - off] : 0;
        __syncthreads();
        sm[threadIdx.x] += t;
        __syncthreads();
    }
    if (i < n) out[i] = sm[threadIdx.x] - v;
    if (threadIdx.x == 1023) bsum[blockIdx.x] = sm[1023];
}
__global__ void k_scan2(int* __restrict__ bsum, int nb) {
    __shared__ int sm[256];
    int v = (threadIdx.x < nb) ? bsum[threadIdx.x] : 0;
    sm[threadIdx.x] = v;
    __syncthreads();
    for (int off = 1; off < 256; off <<= 1) {
        int t = (threadIdx.x >= off) ? sm[threadIdx.x - off] : 0;
        __syncthreads();
        sm[threadIdx.x] += t;
        __syncthreads();
    }
    if (threadIdx.x < nb) bsum[threadIdx.x] = sm[threadIdx.x] - v;
}
__global__ void k_scan3(int* __restrict__ out, const int* __restrict__ bsum,
                        int n, int total, int* __restrict__ cursor) {
    int i = blockIdx.x * 1024 + threadIdx.x;
    if (i < n) {
        int v = out[i] + bsum[blockIdx.x];
        out[i] = v;
        cursor[i] = v;
    }
    if (i == 0) out[n] = total;
}
__global__ void k_scatter(const int* __restrict__ adj, const float* __restrict__ aval,
                          int* __restrict__ cursor, int* __restrict__ col,
                          float* __restrict__ val) {
    int e = blockIdx.x * blockDim.x + threadIdx.x;
    if (e >= EE) return;
    int r = adj[e];
    int p = atomicAdd(&cursor[r], 1);
    col[p] = adj[EE + e];
    val[p] = aval[e];
}
__global__ void k_segoff(const int* __restrict__ seg, int n, int nseg, int* __restrict__ off) {
    int i = blockIdx.x * blockDim.x + threadIdx.x;
    if (i >= n) return;
    int s = seg[i];
    int p = (i == 0) ? -1 : seg[i - 1];
    for (int t = p + 1; t <= s; ++t) off[t] = i;
    if (i == n - 1)
        for (int t = s + 1; t <= nseg; ++t) off[t] = n;
}

// ---------------- SpMM (strided lanes, 4-edge unroll) + bias + BN(+relu)(+BN2) ----------------
__global__ void k_spmm(const float* __restrict__ Xin, float* __restrict__ Yf,
                       __nv_bfloat16* __restrict__ Yhi, __nv_bfloat16* __restrict__ Ylo,
                       const int* __restrict__ rowoff, const int* __restrict__ col,
                       const float* __restrict__ val, const float* __restrict__ bias,
                       const float* __restrict__ vsrc, float* __restrict__ svout,
                       const float* __restrict__ bg, const float* __restrict__ bb,
                       const float* __restrict__ bm, const float* __restrict__ bv,
                       int bnA, int bnB, int M) {
    int gw = (blockIdx.x * blockDim.x + threadIdx.x) >> 5;
    int lane = threadIdx.x & 31;
    if (gw >= M) return;
    int s = rowoff[gw], e = rowoff[gw + 1];
    float acc[4] = {0.f, 0.f, 0.f, 0.f};
    int i = s;
    for (; i + 3 < e; i += 4) {
        int c0 = col[i], c1 = col[i + 1], c2 = col[i + 2], c3 = col[i + 3];
        float v0 = val[i], v1 = val[i + 1], v2 = val[i + 2], v3 = val[i + 3];
        const float* x0 = Xin + (size_t)c0 * CC;
        const float* x1 = Xin + (size_t)c1 * CC;
        const float* x2 = Xin + (size_t)c2 * CC;
        const float* x3 = Xin + (size_t)c3 * CC;
#pragma unroll
        for (int j = 0; j < 4; j++)
            acc[j] += v0 * x0[lane + 32 * j] + v1 * x1[lane + 32 * j] +
                      v2 * x2[lane + 32 * j] + v3 * x3[lane + 32 * j];
    }
    for (; i < e; i++) {
        int c0 = col[i];
        float v0 = val[i];
        const float* x0 = Xin + (size_t)c0 * CC;
#pragma unroll
        for (int j = 0; j < 4; j++) acc[j] += v0 * x0[lane + 32 * j];
    }
    float sdot = 0.f;
#pragma unroll
    for (int j = 0; j < 4; j++) {
        int ch = lane + 32 * j;
        float z = acc[j] + bias[ch];
        z = bn_apply(z, bnA, ch, bg, bb, bm, bv);
        z = fmaxf(z, 0.f);
        if (bnB >= 0) z = bn_apply(z, bnB, ch, bg, bb, bm, bv);
        size_t idx = (size_t)gw * CC + ch;
        if (Yf) Yf[idx] = z;
        if (Yhi) write_split(Yhi, Ylo, idx, z);
        if (vsrc) sdot += z * vsrc[ch];
    }
    if (vsrc) {
        sdot = warp_sum(sdot);
        if (lane == 0) svout[gw] = sdot;
    }
}

// vd[c] = sum_o ad[o] * Wd[o,c]
__global__ void k_vd(const float* __restrict__ Wd, const float* __restrict__ ad,
                     float* __restrict__ vd) {
    int c = threadIdx.x;
    float s = 0.f;
    for (int o = 0; o < CC; o++) s += ad[o] * Wd[o * CC + c];
    vd[c] = s;
}
__global__ void k_rowdot(const float* __restrict__ X, const float* __restrict__ v,
                         float* __restrict__ out, int M) {
    int gw = (blockIdx.x * blockDim.x + threadIdx.x) >> 5;
    int lane = threadIdx.x & 31;
    if (gw >= M) return;
    const float* xr = X + (size_t)gw * CC;
    float s = 0.f;
#pragma unroll
    for (int j = 0; j < 4; j++) s += xr[lane + 32 * j] * v[lane + 32 * j];
    s = warp_sum(s);
    if (lane == 0) out[gw] = s;
}

// ---------------- FUSED pool stage: segsum+relu+BN -> mean (+splits), sdst=mean.vdst,
// then segment softmax over ssrc[i]+sdst and weighted re-aggregate -> q splits ----------------
__global__ void k_fusepool(const float* __restrict__ X, const float* __restrict__ ssrc,
                           const float* __restrict__ vdst, const int* __restrict__ off,
                           int nseg, float* __restrict__ meanout,
                           __nv_bfloat16* __restrict__ phi, __nv_bfloat16* __restrict__ plo,
                           __nv_bfloat16* __restrict__ qhi, __nv_bfloat16* __restrict__ qlo,
                           const float* bg, const float* bb, const float* bm,
                           const float* bv, int bi) {
    int gw = (blockIdx.x * blockDim.x + threadIdx.x) >> 5;
    int lane = threadIdx.x & 31;
    if (gw >= nseg) return;
    int s = off[gw], e = off[gw + 1];

    // pass 1: segment sum (rows contiguous)
    float acc[4] = {0.f, 0.f, 0.f, 0.f};
    for (int i = s; i < e; i++) {
        const float* xr = X + (size_t)i * CC;
#pragma unroll
        for (int j = 0; j < 4; j++) acc[j] += xr[lane + 32 * j];
    }
    // mean = bn(relu(sum)); write mean + splits; sdst partial
    float sdot = 0.f;
#pragma unroll
    for (int j = 0; j < 4; j++) {
        int ch = lane + 32 * j;
        float m = bn_apply(fmaxf(acc[j], 0.f), bi, ch, bg, bb, bm, bv);
        acc[j] = m;
        size_t idx = (size_t)gw * CC + ch;
        meanout[idx] = m;
        write_split(phi, plo, idx, m);
        sdot += m * vdst[ch];
    }
    float sd = warp_sum(sdot);  // sdst for this segment

    // pass 2: segment softmax + weighted aggregate (rows now cache-hot)
    float q[4] = {0.f, 0.f, 0.f, 0.f};
    if (e > s) {
        float mx = -3.402823e38f;
        for (int i = s + lane; i < e; i += 32) {
            float a = ssrc[i] + sd;
            a = a > 0.f ? a : 0.01f * a;
            mx = fmaxf(mx, a);
        }
        mx = warp_max(mx);
        float den = 0.f;
        for (int i = s + lane; i < e; i += 32) {
            float a = ssrc[i] + sd;
            a = a > 0.f ? a : 0.01f * a;
            den += __expf(a - mx);
        }
        den = warp_sum(den);
        float inv = 1.f / den;
        for (int i = s; i < e; i++) {
            float a = ssrc[i] + sd;
            a = a > 0.f ? a : 0.01f * a;
            float w = __expf(a - mx) * inv;
            const float* hr = X + (size_t)i * CC;
#pragma unroll
            for (int j = 0; j < 4; j++) q[j] += w * hr[lane + 32 * j];
        }
    }
#pragma unroll
    for (int j = 0; j < 4; j++)
        write_split(qhi, qlo, (size_t)gw * CC + lane + 32 * j, q[j]);
}

// ---------------- bias + ELU + split (post small GEMM) ----------------
__global__ void k_elu(const float* __restrict__ X, const float* __restrict__ bias,
                      __nv_bfloat16* __restrict__ outhi, __nv_bfloat16* __restrict__ outlo,
                      int n) {
    int idx = blockIdx.x * blockDim.x + threadIdx.x;
    if (idx >= n) return;
    int c = idx & 127;
    float v = X[idx] + bias[c];
    v = v > 0.f ? v : (__expf(v) - 1.f);
    write_split(outhi, outlo, idx, v);
}

// ---------------- GRU gates (+ folded biases) + relu + BN(+BN2) ----------------
__global__ void k_gru(const float* __restrict__ gi, const float* __restrict__ gh,
                      const float* __restrict__ h, const float* __restrict__ bih,
                      const float* __restrict__ bhh, float* __restrict__ outf,
                      __nv_bfloat16* __restrict__ outhi, __nv_bfloat16* __restrict__ outlo,
                      int M, const float* bg, const float* bb, const float* bm,
                      const float* bv, int bnA, int bnB) {
    int idx = blockIdx.x * blockDim.x + threadIdx.x;
    if (idx >= M * CC) return;
    int t = idx >> 7, c = idx & 127;
    const float* gir = gi + (size_t)t * 3 * CC;
    const float* ghr = gh + (size_t)t * 3 * CC;
    float r = 1.f / (1.f + __expf(-(gir[c] + bih[c] + ghr[c] + bhh[c])));
    float z = 1.f / (1.f + __expf(-(gir[CC + c] + bih[CC + c] + ghr[CC + c] + bhh[CC + c])));
    float n = tanhf(gir[2 * CC + c] + bih[2 * CC + c] +
                    r * (ghr[2 * CC + c] + bhh[2 * CC + c]));
    float hv = (1.f - z) * n + z * h[idx];
    float y = fmaxf(hv, 0.f);
    y = bn_apply(y, bnA, c, bg, bb, bm, bv);
    if (bnB >= 0) y = bn_apply(y, bnB, c, bg, bb, bm, bv);
    outf[idx] = y;
    if (outhi) write_split(outhi, outlo, idx, y);
}

// ---------------- predictor ----------------
__global__ void k_pred(const float* __restrict__ mol, const float* __restrict__ W1,
                       const float* __restrict__ b1, const float* __restrict__ W2,
                       const float* __restrict__ b2, float* __restrict__ out) {
    __shared__ float xr[CC];
    __shared__ float hr[64];
    int m = blockIdx.x, t = threadIdx.x;
    xr[t] = mol[(size_t)m * CC + t];
    xr[t + 64] = mol[(size_t)m * CC + t + 64];
    __syncthreads();
    float s = b1[t];
    for (int c = 0; c < CC; c++) s += W1[t * CC + c] * xr[c];
    s = fmaxf(s, 0.f);
    hr[t] = s * W2[t];
    __syncthreads();
    for (int off = 32; off > 0; off >>= 1) {
        if (t < off) hr[t] += hr[t + off];
        __syncthreads();
    }
    if (t == 0) out[m] = hr[0] + b2[0];
}

// ---------------- host ----------------
extern "C" void kernel_launch(void* const* d_in, const int* in_sizes, int n_in,
                              void* d_out, int out_size) {
    if (n_in < 24) return;
    const float *node_attr, *adj_value, *W_gcn, *b_gcn, *bg, *bb, *bm, *bv;
    const float *Wsrc, *Wdst, *asrc, *adst, *gbias, *Wih, *Whh, *bih, *bhh;
    const float *pW1, *pb1, *pW2, *pb2;
    const int *adj_index, *ttb, *tgb;
    if (in_sizes[1] == EE) {
        node_attr = (const float*)d_in[0];  adj_value = (const float*)d_in[1];
        W_gcn = (const float*)d_in[2];      b_gcn = (const float*)d_in[3];
        bg = (const float*)d_in[4];         bb = (const float*)d_in[5];
        bm = (const float*)d_in[6];         bv = (const float*)d_in[7];
        Wsrc = (const float*)d_in[8];       Wdst = (const float*)d_in[9];
        asrc = (const float*)d_in[10];      adst = (const float*)d_in[11];
        gbias = (const float*)d_in[12];     Wih = (const float*)d_in[13];
        Whh = (const float*)d_in[14];       bih = (const float*)d_in[15];
        bhh = (const float*)d_in[16];       pW1 = (const float*)d_in[17];
        pb1 = (const float*)d_in[18];       pW2 = (const float*)d_in[19];
        pb2 = (const float*)d_in[20];       adj_index = (const int*)d_in[21];
        ttb = (const int*)d_in[22];         tgb = (const int*)d_in[23];
    } else {
        node_attr = (const float*)d_in[0];  adj_index = (const int*)d_in[1];
        adj_value = (const float*)d_in[2];  ttb = (const int*)d_in[3];
        tgb = (const int*)d_in[4];          W_gcn = (const float*)d_in[5];
        b_gcn = (const float*)d_in[6];      bg = (const float*)d_in[7];
        bb = (const float*)d_in[8];         bm = (const float*)d_in[9];
        bv = (const float*)d_in[10];        Wsrc = (const float*)d_in[11];
        Wdst = (const float*)d_in[12];      asrc = (const float*)d_in[13];
        adst = (const float*)d_in[14];      gbias = (const float*)d_in[15];
        Wih = (const float*)d_in[16];       Whh = (const float*)d_in[17];
        bih = (const float*)d_in[18];       bhh = (const float*)d_in[19];
        pW1 = (const float*)d_in[20];       pb1 = (const float*)d_in[21];
        pW2 = (const float*)d_in[22];       pb2 = (const float*)d_in[23];
    }

    void* p;
    cudaGetSymbolAddress(&p, g_t1);        float* t1 = (float*)p;
    cudaGetSymbolAddress(&p, g_t2);        float* t2 = (float*)p;
    cudaGetSymbolAddress(&p, g_hs);        float* hsTmp = (float*)p;
    cudaGetSymbolAddress(&p, g_cnt);       int* cnt = (int*)p;
    cudaGetSymbolAddress(&p, g_rowoff);    int* rowoff = (int*)p;
    cudaGetSymbolAddress(&p, g_cursor);    int* cursor = (int*)p;
    cudaGetSymbolAddress(&p, g_bsum);      int* bsum = (int*)p;
    cudaGetSymbolAddress(&p, g_col);       int* col = (int*)p;
    cudaGetSymbolAddress(&p, g_val);       float* val = (float*)p;
    cudaGetSymbolAddress(&p, g_ttoff);     int* ttoff = (int*)p;
    cudaGetSymbolAddress(&p, g_moloff);    int* moloff = (int*)p;
    cudaGetSymbolAddress(&p, g_meanbn_tt); float* meanbn_tt = (float*)p;
    cudaGetSymbolAddress(&p, g_gi_tt);     float* gi_tt = (float*)p;
    cudaGetSymbolAddress(&p, g_gh_tt);     float* gh_tt = (float*)p;
    cudaGetSymbolAddress(&p, g_ttbn);      float* ttbn = (float*)p;
    cudaGetSymbolAddress(&p, g_meanbn_mol);float* meanbn_mol = (float*)p;
    cudaGetSymbolAddress(&p, g_gi_mol);    float* gi_mol = (float*)p;
    cudaGetSymbolAddress(&p, g_gh_mol);    float* gh_mol = (float*)p;
    cudaGetSymbolAddress(&p, g_molout);    float* molout = (float*)p;
    cudaGetSymbolAddress(&p, g_ssrc);      float* ssrc = (float*)p;
    cudaGetSymbolAddress(&p, g_vsrc);      float* vsrc = (float*)p;
    cudaGetSymbolAddress(&p, g_vdst);      float* vdst = (float*)p;
    cudaGetSymbolAddress(&p, g_whi);       __nv_bfloat16* whi = (__nv_bfloat16*)p;
    cudaGetSymbolAddress(&p, g_wlo);       __nv_bfloat16* wlo = (__nv_bfloat16*)p;
    cudaGetSymbolAddress(&p, g_xhi);       __nv_bfloat16* xhi = (__nv_bfloat16*)p;
    cudaGetSymbolAddress(&p, g_xlo);       __nv_bfloat16* xlo = (__nv_bfloat16*)p;
    cudaGetSymbolAddress(&p, g_phi);       __nv_bfloat16* phi = (__nv_bfloat16*)p;
    cudaGetSymbolAddress(&p, g_plo);       __nv_bfloat16* plo = (__nv_bfloat16*)p;
    cudaGetSymbolAddress(&p, g_ghi);       __nv_bfloat16* ghi = (__nv_bfloat16*)p;
    cudaGetSymbolAddress(&p, g_glo);       __nv_bfloat16* glo = (__nv_bfloat16*)p;
    cudaGetSymbolAddress(&p, g_qhi);       __nv_bfloat16* qhi = (__nv_bfloat16*)p;
    cudaGetSymbolAddress(&p, g_qlo);       __nv_bfloat16* qlo = (__nv_bfloat16*)p;
    float* outp = (float*)d_out;

    static cudaStream_t s1 = nullptr;
    static cudaEvent_t ev[8];
    if (s1 == nullptr) {
        cudaStreamCreateWithFlags(&s1, cudaStreamNonBlocking);
        for (int i = 0; i < 8; i++) cudaEventCreateWithFlags(&ev[i], cudaEventDisableTiming);
    }
    auto fork = [&](int i) {
        cudaEventRecord(ev[i], 0);
        cudaStreamWaitEvent(s1, ev[i], 0);
    };
    auto join = [&](int i) {
        cudaEventRecord(ev[i], s1);
        cudaStreamWaitEvent((cudaStream_t)0, ev[i], 0);
    };

    cudaFuncSetAttribute(k_gemm_tc, cudaFuncAttributeMaxDynamicSharedMemorySize, GEMM_SMEM);

    auto gemm = [&](const __nv_bfloat16* xh, const __nv_bfloat16* xl, int wrow,
                    float* Y, int M, int Nout) {
        int ntiles = (M + 127) / 128;
        int gy = Nout / 128;
        int gxmax = 148 / gy; if (gxmax < 1) gxmax = 1;
        int gx = ntiles < gxmax ? ntiles : gxmax;
        dim3 grid(gx, gy, 1);
        k_gemm_tc<<<grid, 256, GEMM_SMEM>>>(xh, xl, whi + (size_t)wrow * 128,
                                            wlo + (size_t)wrow * 128, Y, M, Nout,
                                            nullptr, nullptr, nullptr, nullptr, nullptr);
    };
    auto gemm2 = [&](const __nv_bfloat16* xh, const __nv_bfloat16* xl, int wrow, float* Y,
                     const __nv_bfloat16* xh2, const __nv_bfloat16* xl2, int wrow2, float* Y2,
                     int M, int Nout) {
        int ntiles = (M + 127) / 128;
        int gy = Nout / 128;
        int gxmax = 148 / (gy * 2); if (gxmax < 1) gxmax = 1;
        int gx = ntiles < gxmax ? ntiles : gxmax;
        dim3 grid(gx, gy, 2);
        k_gemm_tc<<<grid, 256, GEMM_SMEM>>>(xh, xl, whi + (size_t)wrow * 128,
                                            wlo + (size_t)wrow * 128, Y, M, Nout,
                                            xh2, xl2, whi + (size_t)wrow2 * 128,
                                            wlo + (size_t)wrow2 * 128, Y2);
    };

    // ===== phase 1: CSR build (s1)  ||  wsplit+xsplit+gemm0 (main) =====
    fork(0);
    k_zero_int<<<(NN + 255) / 256, 256, 0, s1>>>(cnt, NN);
    k_hist<<<(EE + 255) / 256, 256, 0, s1>>>(adj_index, cnt);
    k_scan1<<<196, 1024, 0, s1>>>(cnt, rowoff, bsum, NN);
    k_scan2<<<1, 256, 0, s1>>>(bsum, 196);
    k_scan3<<<196, 1024, 0, s1>>>(rowoff, bsum, NN, EE, cursor);
    k_scatter<<<(EE + 255) / 256, 256, 0, s1>>>(adj_index, adj_value, cursor, col, val);
    k_segoff<<<(NN + 255) / 256, 256, 0, s1>>>(ttb, NN, NTTS, ttoff);
    k_segoff<<<(NTTS + 255) / 256, 256, 0, s1>>>(tgb, NTTS, NMOLS, moloff);
    k_vd<<<1, 128, 0, s1>>>(Wsrc, asrc, vsrc);
    k_vd<<<1, 128, 0, s1>>>(Wdst, adst, vdst);

    k_wsplit<<<1024, 256>>>(W_gcn, Wsrc, Wih, Whh, whi, wlo);
    k_xsplit<<<(NN * 32 + 255) / 256, 256>>>(node_attr, xhi, xlo, NN * 32);
    gemm(xhi, xlo, WR_G0, t1, NN, 128);
    join(1);

    // ===== GCN layers =====
    k_spmm<<<NN / 8, 256>>>(t1, nullptr, xhi, xlo, rowoff, col, val, b_gcn,
                            nullptr, nullptr, bg, bb, bm, bv, 0, -1, NN);
    gemm(xhi, xlo, WR_G1, t1, NN, 128);
    k_spmm<<<NN / 8, 256>>>(t1, t2, nullptr, nullptr, rowoff, col, val, b_gcn + CC,
                            vsrc, ssrc, bg, bb, bm, bv, 1, 2, NN);

    // ===== tt stage: fused pool (segsum+BN -> sdst -> softmax aggregate) =====
    k_fusepool<<<(NTTS * 32 + 255) / 256, 256>>>(t2, ssrc, vdst, ttoff, NTTS,
                                                 meanbn_tt, phi, plo, qhi, qlo,
                                                 bg, bb, bm, bv, 3);
    gemm(qhi, qlo, WR_S0, hsTmp, NTTS, 128);
    k_elu<<<(NTTS * CC + 255) / 256, 256>>>(hsTmp, gbias, ghi, glo, NTTS * CC);
    gemm2(ghi, glo, WR_IH0, gi_tt, phi, plo, WR_HH0, gh_tt, NTTS, 384);
    k_gru<<<(NTTS * CC + 255) / 256, 256>>>(gi_tt, gh_tt, meanbn_tt, bih, bhh,
                                            ttbn, ghi, glo, NTTS, bg, bb, bm, bv, 4, 5);

    // ===== mol stage: side-stream ssrc/vd prep overlaps tt GRU GEMMs =====
    fork(4);
    k_vd<<<1, 128, 0, s1>>>(Wsrc + CC * CC, asrc + CC, vsrc);
    k_vd<<<1, 128, 0, s1>>>(Wdst + CC * CC, adst + CC, vdst);
    join(5);
    k_rowdot<<<(NTTS * 32 + 255) / 256, 256>>>(ttbn, vsrc, ssrc, NTTS);
    k_fusepool<<<(NMOLS * 32 + 255) / 256, 256>>>(ttbn, ssrc, vdst, moloff, NMOLS,
                                                  meanbn_mol, phi, plo, qhi, qlo,
                                                  bg, bb, bm, bv, 6);
    gemm(qhi, qlo, WR_S1, hsTmp, NMOLS, 128);
    k_elu<<<(NMOLS * CC + 255) / 256, 256>>>(hsTmp, gbias + CC, ghi, glo, NMOLS * CC);
    gemm2(ghi, glo, WR_IH1, gi_mol, phi, plo, WR_HH1, gh_mol, NMOLS, 384);
    k_gru<<<(NMOLS * CC + 255) / 256, 256>>>(gi_mol, gh_mol, meanbn_mol, bih + 3 * CC,
                                             bhh + 3 * CC, molout, nullptr, nullptr,
                                             NMOLS, bg, bb, bm, bv, 7, -1);

    // predictor
    k_pred<<<NMOLS, 64>>>(molout, pW1, pb1, pW2, pb2, outp);
}

// round 17
// speedup vs baseline: 1.2034x; 1.0510x over previous
#include <cuda_runtime.h>
#include <cuda_bf16.h>
#include <mma.h>
#include <stdint.h>
#include <stddef.h>
#include <math.h>

using namespace nvcuda;

#define NN 200000
#define EE 1600000
#define CC 128
#define NTTS 20000
#define NMOLS 2000

// ---------------- static device scratch ----------------
__device__ float g_t1[(size_t)NN * CC];
__device__ float g_t2[(size_t)NN * CC];
__device__ float g_hs[(size_t)NTTS * CC];   // small GEMM output (pre-ELU)
__device__ int   g_cnt[NN];
__device__ int   g_rowoff[NN + 1];
__device__ int   g_cursor[NN];
__device__ int   g_bsum[256];
__device__ int   g_col[EE];
__device__ float g_val[EE];
__device__ int   g_ttoff[NTTS + 1];
__device__ int   g_moloff[NMOLS + 1];
__device__ float g_meanbn_tt[(size_t)NTTS * CC];
__device__ float g_gi_tt[(size_t)NTTS * 3 * CC];
__device__ float g_gh_tt[(size_t)NTTS * 3 * CC];
__device__ float g_ttbn[(size_t)NTTS * CC];
__device__ float g_meanbn_mol[(size_t)NMOLS * CC];
__device__ float g_gi_mol[(size_t)NMOLS * 3 * CC];
__device__ float g_gh_mol[(size_t)NMOLS * 3 * CC];
__device__ float g_molout[(size_t)NMOLS * CC];
__device__ float g_ssrc[NN];
__device__ float g_vsrc[CC];
__device__ float g_vdst[CC];
__device__ __nv_bfloat16 g_whi[2048 * 128];
__device__ __nv_bfloat16 g_wlo[2048 * 128];
__device__ __nv_bfloat16 g_xhi[(size_t)NN * CC];
__device__ __nv_bfloat16 g_xlo[(size_t)NN * CC];
__device__ __nv_bfloat16 g_phi[(size_t)NTTS * CC];
__device__ __nv_bfloat16 g_plo[(size_t)NTTS * CC];
__device__ __nv_bfloat16 g_ghi[(size_t)NTTS * CC];
__device__ __nv_bfloat16 g_glo[(size_t)NTTS * CC];
__device__ __nv_bfloat16 g_qhi[(size_t)NTTS * CC];
__device__ __nv_bfloat16 g_qlo[(size_t)NTTS * CC];

#define WR_G0 0
#define WR_G1 128
#define WR_S0 256
#define WR_S1 384
#define WR_IH0 512
#define WR_IH1 896
#define WR_HH0 1280
#define WR_HH1 1664

// ---------------- helpers ----------------
__device__ __forceinline__ uint32_t smem_u32(const void* p) {
    uint32_t a;
    asm("{ .reg .u64 t; cvta.to.shared.u64 t, %1; cvt.u32.u64 %0, t; }" : "=r"(a) : "l"(p));
    return a;
}
__device__ __forceinline__ void cp16(uint32_t saddr, const void* g) {
    asm volatile("cp.async.cg.shared.global [%0], [%1], 16;" :: "r"(saddr), "l"(g));
}
#define CP_COMMIT asm volatile("cp.async.commit_group;" ::: "memory")
#define CP_WAIT(n) asm volatile("cp.async.wait_group %0;" :: "n"(n) : "memory")

__device__ __forceinline__ void write_split(__nv_bfloat16* hi, __nv_bfloat16* lo,
                                            size_t idx, float z) {
    __nv_bfloat16 h = __float2bfloat16(z);
    hi[idx] = h;
    lo[idx] = __float2bfloat16(z - __bfloat162float(h));
}

// ---------------- weight split ----------------
__global__ void k_wsplit(const float* __restrict__ Wg, const float* __restrict__ Ws,
                         const float* __restrict__ Wih, const float* __restrict__ Whh,
                         __nv_bfloat16* __restrict__ hi, __nv_bfloat16* __restrict__ lo) {
    int idx = blockIdx.x * blockDim.x + threadIdx.x;
    int row = idx >> 7, c = idx & 127;
    float w;
    if (row < 256)       w = Wg[(size_t)row * 128 + c];
    else if (row < 512)  w = Ws[(size_t)(row - 256) * 128 + c];
    else if (row < 1280) w = Wih[(size_t)(row - 512) * 128 + c];
    else                 w = Whh[(size_t)(row - 1280) * 128 + c];
    write_split(hi, lo, idx, w);
}

// ---------------- wmma GEMM: Y = X @ W^T, 3-term bf16 split.
// bf16-split input: A double-buffered. fp32 input (Xlo==nullptr): single-buffered
// fp32 staging + in-smem convert, next-tile load overlaps mma. Dual-batch via z. ----------------
#define LDA 136
#define TILE_BYTES (128 * LDA * 2)
#define BH_OFF 0
#define BL_OFF TILE_BYTES
#define A_OFF (2 * TILE_BYTES)
#define GEMM_SMEM (A_OFF + 4 * TILE_BYTES)   // 208,896 B
#define STG_LD 132                            // fp32 staging row stride (floats)

__global__ __launch_bounds__(256) void k_gemm_tc(
    const __nv_bfloat16* __restrict__ Xhi, const __nv_bfloat16* __restrict__ Xlo,
    const __nv_bfloat16* __restrict__ bhi, const __nv_bfloat16* __restrict__ blo,
    float* __restrict__ Y, int M, int Nout,
    const __nv_bfloat16* __restrict__ X2hi, const __nv_bfloat16* __restrict__ X2lo,
    const __nv_bfloat16* __restrict__ b2hi, const __nv_bfloat16* __restrict__ b2lo,
    float* __restrict__ Y2) {
    extern __shared__ char smem[];
    if (blockIdx.z == 1) {
        Xhi = X2hi; Xlo = X2lo; bhi = b2hi; blo = b2lo; Y = Y2;
    }
    __nv_bfloat16* Bh = reinterpret_cast<__nv_bfloat16*>(smem + BH_OFF);
    __nv_bfloat16* Bl = reinterpret_cast<__nv_bfloat16*>(smem + BL_OFF);

    int tid = threadIdx.x, wid = tid >> 5;
    int tn = blockIdx.y;
    int ntiles = (M + 127) >> 7;
    if ((int)blockIdx.x >= ntiles) return;
    uint32_t sb = smem_u32(smem);

    for (int i = tid; i < 128 * 16; i += 256) {
        int r = i >> 4, c = i & 15;
        cp16(sb + BH_OFF + r * (LDA * 2) + c * 16, &bhi[(size_t)(tn * 128 + r) * 128 + c * 8]);
        cp16(sb + BL_OFF + r * (LDA * 2) + c * 16, &blo[(size_t)(tn * 128 + r) * 128 + c * 8]);
    }
    CP_COMMIT;

    int wm = wid & 1, wn = wid >> 1;

    if (Xlo != nullptr) {
        // ===== bf16-split input: double-buffered A =====
        auto load_a = [&](int tm, int st) {
            int row0 = tm * 128;
            uint32_t base = sb + A_OFF + st * 2 * TILE_BYTES;
            for (int i = tid; i < 128 * 16; i += 256) {
                int r = i >> 4, c = i & 15;
                int gr = row0 + r;
                if (gr >= M) gr = M - 1;
                cp16(base + r * (LDA * 2) + c * 16, &Xhi[(size_t)gr * 128 + c * 8]);
                cp16(base + TILE_BYTES + r * (LDA * 2) + c * 16, &Xlo[(size_t)gr * 128 + c * 8]);
            }
            CP_COMMIT;
        };
        load_a(blockIdx.x, 0);
        int st = 0;
        for (int tm = blockIdx.x; tm < ntiles; tm += gridDim.x, st ^= 1) {
            int tmn = tm + gridDim.x;
            if (tmn < ntiles) {
                load_a(tmn, st ^ 1);
                CP_WAIT(1);
            } else {
                CP_WAIT(0);
            }
            __syncthreads();

            __nv_bfloat16* Ah = reinterpret_cast<__nv_bfloat16*>(smem + A_OFF + st * 2 * TILE_BYTES);
            __nv_bfloat16* Al = Ah + 128 * LDA;

            wmma::fragment<wmma::accumulator, 16, 16, 16, float> cf[4][2];
#pragma unroll
            for (int i = 0; i < 4; i++)
#pragma unroll
                for (int j = 0; j < 2; j++) wmma::fill_fragment(cf[i][j], 0.f);
            const __nv_bfloat16* Aterm[3] = {Ah, Ah, Al};
            const __nv_bfloat16* Bterm[3] = {Bh, Bl, Bh};
#pragma unroll
            for (int t = 0; t < 3; t++) {
                const __nv_bfloat16* As = Aterm[t];
                const __nv_bfloat16* Bs = Bterm[t];
#pragma unroll
                for (int k0 = 0; k0 < 128; k0 += 16) {
                    wmma::fragment<wmma::matrix_a, 16, 16, 16, __nv_bfloat16, wmma::row_major> a[4];
                    wmma::fragment<wmma::matrix_b, 16, 16, 16, __nv_bfloat16, wmma::col_major> b[2];
#pragma unroll
                    for (int i = 0; i < 4; i++)
                        wmma::load_matrix_sync(a[i], &As[(wm * 64 + i * 16) * LDA + k0], LDA);
#pragma unroll
                    for (int j = 0; j < 2; j++)
                        wmma::load_matrix_sync(b[j], &Bs[(wn * 32 + j * 16) * LDA + k0], LDA);
#pragma unroll
                    for (int i = 0; i < 4; i++)
#pragma unroll
                        for (int j = 0; j < 2; j++) wmma::mma_sync(cf[i][j], a[i], b[j], cf[i][j]);
                }
            }
            int row0 = tm * 128;
#pragma unroll
            for (int i = 0; i < 4; i++) {
                int row = row0 + wm * 64 + i * 16;
                if (row + 16 <= M) {
#pragma unroll
                    for (int j = 0; j < 2; j++)
                        wmma::store_matrix_sync(&Y[(size_t)row * Nout + tn * 128 + wn * 32 + j * 16],
                                                cf[i][j], Nout, wmma::mem_row_major);
                }
            }
            __syncthreads();
        }
    } else {
        // ===== fp32 input: single-buffered staging + in-smem convert =====
        const float* Xf = reinterpret_cast<const float*>(Xhi);
        float* stage = reinterpret_cast<float*>(smem + A_OFF);           // [128][STG_LD]
        __nv_bfloat16* Ah = reinterpret_cast<__nv_bfloat16*>(smem + A_OFF + 128 * STG_LD * 4);
        __nv_bfloat16* Al = Ah + 128 * LDA;

        auto load_stage = [&](int tm) {
            int row0 = tm * 128;
            for (int i = tid; i < 128 * 32; i += 256) {
                int r = i >> 5, c = i & 31;
                int gr = row0 + r;
                if (gr >= M) gr = M - 1;
                cp16(sb + A_OFF + (r * STG_LD + c * 4) * 4, &Xf[(size_t)gr * 128 + c * 4]);
            }
            CP_COMMIT;
        };
        load_stage(blockIdx.x);
        for (int tm = blockIdx.x; tm < ntiles; tm += gridDim.x) {
            CP_WAIT(0);
            __syncthreads();
            // convert staging -> Ah/Al
            for (int i = tid; i < 128 * 32; i += 256) {
                int r = i >> 5, c = i & 31;
                float4 x = *reinterpret_cast<float4*>(&stage[r * STG_LD + c * 4]);
                __nv_bfloat162 h01 = __floats2bfloat162_rn(x.x, x.y);
                __nv_bfloat162 h23 = __floats2bfloat162_rn(x.z, x.w);
                __nv_bfloat162 l01 = __floats2bfloat162_rn(x.x - __bfloat162float(h01.x),
                                                           x.y - __bfloat162float(h01.y));
                __nv_bfloat162 l23 = __floats2bfloat162_rn(x.z - __bfloat162float(h23.x),
                                                           x.w - __bfloat162float(h23.y));
                *reinterpret_cast<uint2*>(&Ah[r * LDA + c * 4]) =
                    make_uint2(*reinterpret_cast<uint32_t*>(&h01), *reinterpret_cast<uint32_t*>(&h23));
                *reinterpret_cast<uint2*>(&Al[r * LDA + c * 4]) =
                    make_uint2(*reinterpret_cast<uint32_t*>(&l01), *reinterpret_cast<uint32_t*>(&l23));
            }
            __syncthreads();
            int tmn = tm + gridDim.x;
            if (tmn < ntiles) load_stage(tmn);  // flies during mma

            wmma::fragment<wmma::accumulator, 16, 16, 16, float> cf[4][2];
#pragma unroll
            for (int i = 0; i < 4; i++)
#pragma unroll
                for (int j = 0; j < 2; j++) wmma::fill_fragment(cf[i][j], 0.f);
            const __nv_bfloat16* Aterm[3] = {Ah, Ah, Al};
            const __nv_bfloat16* Bterm[3] = {Bh, Bl, Bh};
#pragma unroll
            for (int t = 0; t < 3; t++) {
                const __nv_bfloat16* As = Aterm[t];
                const __nv_bfloat16* Bs = Bterm[t];
#pragma unroll
                for (int k0 = 0; k0 < 128; k0 += 16) {
                    wmma::fragment<wmma::matrix_a, 16, 16, 16, __nv_bfloat16, wmma::row_major> a[4];
                    wmma::fragment<wmma::matrix_b, 16, 16, 16, __nv_bfloat16, wmma::col_major> b[2];
#pragma unroll
                    for (int i = 0; i < 4; i++)
                        wmma::load_matrix_sync(a[i], &As[(wm * 64 + i * 16) * LDA + k0], LDA);
#pragma unroll
                    for (int j = 0; j < 2; j++)
                        wmma::load_matrix_sync(b[j], &Bs[(wn * 32 + j * 16) * LDA + k0], LDA);
#pragma unroll
                    for (int i = 0; i < 4; i++)
#pragma unroll
                        for (int j = 0; j < 2; j++) wmma::mma_sync(cf[i][j], a[i], b[j], cf[i][j]);
                }
            }
            int row0 = tm * 128;
#pragma unroll
            for (int i = 0; i < 4; i++) {
                int row = row0 + wm * 64 + i * 16;
                if (row + 16 <= M) {
#pragma unroll
                    for (int j = 0; j < 2; j++)
                        wmma::store_matrix_sync(&Y[(size_t)row * Nout + tn * 128 + wn * 32 + j * 16],
                                                cf[i][j], Nout, wmma::mem_row_major);
                }
            }
            __syncthreads();  // Ah/Al free; staging being filled by in-flight cp.async
        }
    }
}

// ---------------- small helpers ----------------
__device__ __forceinline__ float bn_apply(float x, int idx, int ch,
                                          const float* g, const float* b,
                                          const float* m, const float* v) {
    float sc = g[idx * CC + ch] * rsqrtf(v[idx * CC + ch] + 1e-5f);
    return (x - m[idx * CC + ch]) * sc + b[idx * CC + ch];
}
__device__ __forceinline__ float warp_max(float v) {
#pragma unroll
    for (int o = 16; o > 0; o >>= 1) v = fmaxf(v, __shfl_xor_sync(0xffffffffu, v, o));
    return v;
}
__device__ __forceinline__ float warp_sum(float v) {
#pragma unroll
    for (int o = 16; o > 0; o >>= 1) v += __shfl_xor_sync(0xffffffffu, v, o);
    return v;
}

// ---------------- CSR build ----------------
__global__ void k_zero_int(int* p, int n) {
    int i = blockIdx.x * blockDim.x + threadIdx.x;
    if (i < n) p[i] = 0;
}
__global__ void k_hist(const int* __restrict__ idx0, int* __restrict__ cnt) {
    int e = blockIdx.x * blockDim.x + threadIdx.x;
    if (e < EE) atomicAdd(&cnt[idx0[e]], 1);
}
__global__ void k_scan1(const int* __restrict__ in, int* __restrict__ out,
                        int* __restrict__ bsum, int n) {
    __shared__ int sm[1024];
    int i = blockIdx.x * 1024 + threadIdx.x;
    int v = (i < n) ? in[i] : 0;
    sm[threadIdx.x] = v;
    __syncthreads();
    for (int off = 1; off < 1024; off <<= 1) {
        int t = (threadIdx.x >= off) ? sm[threadIdx.x - off] : 0;
        __syncthreads();
        sm[threadIdx.x] += t;
        __syncthreads();
    }
    if (i < n) out[i] = sm[threadIdx.x] - v;
    if (threadIdx.x == 1023) bsum[blockIdx.x] = sm[1023];
}
__global__ void k_scan2(int* __restrict__ bsum, int nb) {
    __shared__ int sm[256];
    int v = (threadIdx.x < nb) ? bsum[threadIdx.x] : 0;
    sm[threadIdx.x] = v;
    __syncthreads();
    for (int off = 1; off < 256; off <<= 1) {
        int t = (threadIdx.x >= off) ? sm[threadIdx.x - off] : 0;
        __syncthreads();
        sm[threadIdx.x] += t;
        __syncthreads();
    }
    if (threadIdx.x < nb) bsum[threadIdx.x] = sm[threadIdx.x] - v;
}
__global__ void k_scan3(int* __restrict__ out, const int* __restrict__ bsum,
                        int n, int total, int* __restrict__ cursor) {
    int i = blockIdx.x * 1024 + threadIdx.x;
    if (i < n) {
        int v = out[i] + bsum[blockIdx.x];
        out[i] = v;
        cursor[i] = v;
    }
    if (i == 0) out[n] = total;
}
__global__ void k_scatter(const int* __restrict__ adj, const float* __restrict__ aval,
                          int* __restrict__ cursor, int* __restrict__ col,
                          float* __restrict__ val) {
    int e = blockIdx.x * blockDim.x + threadIdx.x;
    if (e >= EE) return;
    int r = adj[e];
    int p = atomicAdd(&cursor[r], 1);
    col[p] = adj[EE + e];
    val[p] = aval[e];
}
__global__ void k_segoff(const int* __restrict__ seg, int n, int nseg, int* __restrict__ off) {
    int i = blockIdx.x * blockDim.x + threadIdx.x;
    if (i >= n) return;
    int s = seg[i];
    int p = (i == 0) ? -1 : seg[i - 1];
    for (int t = p + 1; t <= s; ++t) off[t] = i;
    if (i == n - 1)
        for (int t = s + 1; t <= nseg; ++t) off[t] = n;
}

// ---------------- SpMM (strided lanes, 4-edge unroll) + bias + BN(+relu)(+BN2) ----------------
__global__ void k_spmm(const float* __restrict__ Xin, float* __restrict__ Yf,
                       __nv_bfloat16* __restrict__ Yhi, __nv_bfloat16* __restrict__ Ylo,
                       const int* __restrict__ rowoff, const int* __restrict__ col,
                       const float* __restrict__ val, const float* __restrict__ bias,
                       const float* __restrict__ vsrc, float* __restrict__ svout,
                       const float* __restrict__ bg, const float* __restrict__ bb,
                       const float* __restrict__ bm, const float* __restrict__ bv,
                       int bnA, int bnB, int M) {
    int gw = (blockIdx.x * blockDim.x + threadIdx.x) >> 5;
    int lane = threadIdx.x & 31;
    if (gw >= M) return;
    int s = rowoff[gw], e = rowoff[gw + 1];
    float acc[4] = {0.f, 0.f, 0.f, 0.f};
    int i = s;
    for (; i + 3 < e; i += 4) {
        int c0 = col[i], c1 = col[i + 1], c2 = col[i + 2], c3 = col[i + 3];
        float v0 = val[i], v1 = val[i + 1], v2 = val[i + 2], v3 = val[i + 3];
        const float* x0 = Xin + (size_t)c0 * CC;
        const float* x1 = Xin + (size_t)c1 * CC;
        const float* x2 = Xin + (size_t)c2 * CC;
        const float* x3 = Xin + (size_t)c3 * CC;
#pragma unroll
        for (int j = 0; j < 4; j++)
            acc[j] += v0 * x0[lane + 32 * j] + v1 * x1[lane + 32 * j] +
                      v2 * x2[lane + 32 * j] + v3 * x3[lane + 32 * j];
    }
    for (; i < e; i++) {
        int c0 = col[i];
        float v0 = val[i];
        const float* x0 = Xin + (size_t)c0 * CC;
#pragma unroll
        for (int j = 0; j < 4; j++) acc[j] += v0 * x0[lane + 32 * j];
    }
    float sdot = 0.f;
#pragma unroll
    for (int j = 0; j < 4; j++) {
        int ch = lane + 32 * j;
        float z = acc[j] + bias[ch];
        z = bn_apply(z, bnA, ch, bg, bb, bm, bv);
        z = fmaxf(z, 0.f);
        if (bnB >= 0) z = bn_apply(z, bnB, ch, bg, bb, bm, bv);
        size_t idx = (size_t)gw * CC + ch;
        if (Yf) Yf[idx] = z;
        if (Yhi) write_split(Yhi, Ylo, idx, z);
        if (vsrc) sdot += z * vsrc[ch];
    }
    if (vsrc) {
        sdot = warp_sum(sdot);
        if (lane == 0) svout[gw] = sdot;
    }
}

// vd[c] = sum_o ad[o] * Wd[o,c]
__global__ void k_vd(const float* __restrict__ Wd, const float* __restrict__ ad,
                     float* __restrict__ vd) {
    int c = threadIdx.x;
    float s = 0.f;
    for (int o = 0; o < CC; o++) s += ad[o] * Wd[o * CC + c];
    vd[c] = s;
}
__global__ void k_rowdot(const float* __restrict__ X, const float* __restrict__ v,
                         float* __restrict__ out, int M) {
    int gw = (blockIdx.x * blockDim.x + threadIdx.x) >> 5;
    int lane = threadIdx.x & 31;
    if (gw >= M) return;
    const float* xr = X + (size_t)gw * CC;
    float s = 0.f;
#pragma unroll
    for (int j = 0; j < 4; j++) s += xr[lane + 32 * j] * v[lane + 32 * j];
    s = warp_sum(s);
    if (lane == 0) out[gw] = s;
}

// ---------------- FUSED pool stage ----------------
__global__ void k_fusepool(const float* __restrict__ X, const float* __restrict__ ssrc,
                           const float* __restrict__ vdst, const int* __restrict__ off,
                           int nseg, float* __restrict__ meanout,
                           __nv_bfloat16* __restrict__ phi, __nv_bfloat16* __restrict__ plo,
                           __nv_bfloat16* __restrict__ qhi, __nv_bfloat16* __restrict__ qlo,
                           const float* bg, const float* bb, const float* bm,
                           const float* bv, int bi) {
    int gw = (blockIdx.x * blockDim.x + threadIdx.x) >> 5;
    int lane = threadIdx.x & 31;
    if (gw >= nseg) return;
    int s = off[gw], e = off[gw + 1];

    float acc[4] = {0.f, 0.f, 0.f, 0.f};
    for (int i = s; i < e; i++) {
        const float* xr = X + (size_t)i * CC;
#pragma unroll
        for (int j = 0; j < 4; j++) acc[j] += xr[lane + 32 * j];
    }
    float sdot = 0.f;
#pragma unroll
    for (int j = 0; j < 4; j++) {
        int ch = lane + 32 * j;
        float m = bn_apply(fmaxf(acc[j], 0.f), bi, ch, bg, bb, bm, bv);
        acc[j] = m;
        size_t idx = (size_t)gw * CC + ch;
        meanout[idx] = m;
        write_split(phi, plo, idx, m);
        sdot += m * vdst[ch];
    }
    float sd = warp_sum(sdot);

    float q[4] = {0.f, 0.f, 0.f, 0.f};
    if (e > s) {
        float mx = -3.402823e38f;
        for (int i = s + lane; i < e; i += 32) {
            float a = ssrc[i] + sd;
            a = a > 0.f ? a : 0.01f * a;
            mx = fmaxf(mx, a);
        }
        mx = warp_max(mx);
        float den = 0.f;
        for (int i = s + lane; i < e; i += 32) {
            float a = ssrc[i] + sd;
            a = a > 0.f ? a : 0.01f * a;
            den += __expf(a - mx);
        }
        den = warp_sum(den);
        float inv = 1.f / den;
        for (int i = s; i < e; i++) {
            float a = ssrc[i] + sd;
            a = a > 0.f ? a : 0.01f * a;
            float w = __expf(a - mx) * inv;
            const float* hr = X + (size_t)i * CC;
#pragma unroll
            for (int j = 0; j < 4; j++) q[j] += w * hr[lane + 32 * j];
        }
    }
#pragma unroll
    for (int j = 0; j < 4; j++)
        write_split(qhi, qlo, (size_t)gw * CC + lane + 32 * j, q[j]);
}

// ---------------- bias + ELU + split ----------------
__global__ void k_elu(const float* __restrict__ X, const float* __restrict__ bias,
                      __nv_bfloat16* __restrict__ outhi, __nv_bfloat16* __restrict__ outlo,
                      int n) {
    int idx = blockIdx.x * blockDim.x + threadIdx.x;
    if (idx >= n) return;
    int c = idx & 127;
    float v = X[idx] + bias[c];
    v = v > 0.f ? v : (__expf(v) - 1.f);
    write_split(outhi, outlo, idx, v);
}

// ---------------- GRU gates (+ folded biases) + relu + BN(+BN2) ----------------
__global__ void k_gru(const float* __restrict__ gi, const float* __restrict__ gh,
                      const float* __restrict__ h, const float* __restrict__ bih,
                      const float* __restrict__ bhh, float* __restrict__ outf,
                      __nv_bfloat16* __restrict__ outhi, __nv_bfloat16* __restrict__ outlo,
                      int M, const float* bg, const float* bb, const float* bm,
                      const float* bv, int bnA, int bnB) {
    int idx = blockIdx.x * blockDim.x + threadIdx.x;
    if (idx >= M * CC) return;
    int t = idx >> 7, c = idx & 127;
    const float* gir = gi + (size_t)t * 3 * CC;
    const float* ghr = gh + (size_t)t * 3 * CC;
    float r = 1.f / (1.f + __expf(-(gir[c] + bih[c] + ghr[c] + bhh[c])));
    float z = 1.f / (1.f + __expf(-(gir[CC + c] + bih[CC + c] + ghr[CC + c] + bhh[CC + c])));
    float n = tanhf(gir[2 * CC + c] + bih[2 * CC + c] +
                    r * (ghr[2 * CC + c] + bhh[2 * CC + c]));
    float hv = (1.f - z) * n + z * h[idx];
    float y = fmaxf(hv, 0.f);
    y = bn_apply(y, bnA, c, bg, bb, bm, bv);
    if (bnB >= 0) y = bn_apply(y, bnB, c, bg, bb, bm, bv);
    outf[idx] = y;
    if (outhi) write_split(outhi, outlo, idx, y);
}

// ---------------- predictor ----------------
__global__ void k_pred(const float* __restrict__ mol, const float* __restrict__ W1,
                       const float* __restrict__ b1, const float* __restrict__ W2,
                       const float* __restrict__ b2, float* __restrict__ out) {
    __shared__ float xr[CC];
    __shared__ float hr[64];
    int m = blockIdx.x, t = threadIdx.x;
    xr[t] = mol[(size_t)m * CC + t];
    xr[t + 64] = mol[(size_t)m * CC + t + 64];
    __syncthreads();
    float s = b1[t];
    for (int c = 0; c < CC; c++) s += W1[t * CC + c] * xr[c];
    s = fmaxf(s, 0.f);
    hr[t] = s * W2[t];
    __syncthreads();
    for (int off = 32; off > 0; off >>= 1) {
        if (t < off) hr[t] += hr[t + off];
        __syncthreads();
    }
    if (t == 0) out[m] = hr[0] + b2[0];
}

// ---------------- host ----------------
extern "C" void kernel_launch(void* const* d_in, const int* in_sizes, int n_in,
                              void* d_out, int out_size) {
    if (n_in < 24) return;
    const float *node_attr, *adj_value, *W_gcn, *b_gcn, *bg, *bb, *bm, *bv;
    const float *Wsrc, *Wdst, *asrc, *adst, *gbias, *Wih, *Whh, *bih, *bhh;
    const float *pW1, *pb1, *pW2, *pb2;
    const int *adj_index, *ttb, *tgb;
    if (in_sizes[1] == EE) {
        node_attr = (const float*)d_in[0];  adj_value = (const float*)d_in[1];
        W_gcn = (const float*)d_in[2];      b_gcn = (const float*)d_in[3];
        bg = (const float*)d_in[4];         bb = (const float*)d_in[5];
        bm = (const float*)d_in[6];         bv = (const float*)d_in[7];
        Wsrc = (const float*)d_in[8];       Wdst = (const float*)d_in[9];
        asrc = (const float*)d_in[10];      adst = (const float*)d_in[11];
        gbias = (const float*)d_in[12];     Wih = (const float*)d_in[13];
        Whh = (const float*)d_in[14];       bih = (const float*)d_in[15];
        bhh = (const float*)d_in[16];       pW1 = (const float*)d_in[17];
        pb1 = (const float*)d_in[18];       pW2 = (const float*)d_in[19];
        pb2 = (const float*)d_in[20];       adj_index = (const int*)d_in[21];
        ttb = (const int*)d_in[22];         tgb = (const int*)d_in[23];
    } else {
        node_attr = (const float*)d_in[0];  adj_index = (const int*)d_in[1];
        adj_value = (const float*)d_in[2];  ttb = (const int*)d_in[3];
        tgb = (const int*)d_in[4];          W_gcn = (const float*)d_in[5];
        b_gcn = (const float*)d_in[6];      bg = (const float*)d_in[7];
        bb = (const float*)d_in[8];         bm = (const float*)d_in[9];
        bv = (const float*)d_in[10];        Wsrc = (const float*)d_in[11];
        Wdst = (const float*)d_in[12];      asrc = (const float*)d_in[13];
        adst = (const float*)d_in[14];      gbias = (const float*)d_in[15];
        Wih = (const float*)d_in[16];       Whh = (const float*)d_in[17];
        bih = (const float*)d_in[18];       bhh = (const float*)d_in[19];
        pW1 = (const float*)d_in[20];       pb1 = (const float*)d_in[21];
        pW2 = (const float*)d_in[22];       pb2 = (const float*)d_in[23];
    }

    void* p;
    cudaGetSymbolAddress(&p, g_t1);        float* t1 = (float*)p;
    cudaGetSymbolAddress(&p, g_t2);        float* t2 = (float*)p;
    cudaGetSymbolAddress(&p, g_hs);        float* hsTmp = (float*)p;
    cudaGetSymbolAddress(&p, g_cnt);       int* cnt = (int*)p;
    cudaGetSymbolAddress(&p, g_rowoff);    int* rowoff = (int*)p;
    cudaGetSymbolAddress(&p, g_cursor);    int* cursor = (int*)p;
    cudaGetSymbolAddress(&p, g_bsum);      int* bsum = (int*)p;
    cudaGetSymbolAddress(&p, g_col);       int* col = (int*)p;
    cudaGetSymbolAddress(&p, g_val);       float* val = (float*)p;
    cudaGetSymbolAddress(&p, g_ttoff);     int* ttoff = (int*)p;
    cudaGetSymbolAddress(&p, g_moloff);    int* moloff = (int*)p;
    cudaGetSymbolAddress(&p, g_meanbn_tt); float* meanbn_tt = (float*)p;
    cudaGetSymbolAddress(&p, g_gi_tt);     float* gi_tt = (float*)p;
    cudaGetSymbolAddress(&p, g_gh_tt);     float* gh_tt = (float*)p;
    cudaGetSymbolAddress(&p, g_ttbn);      float* ttbn = (float*)p;
    cudaGetSymbolAddress(&p, g_meanbn_mol);float* meanbn_mol = (float*)p;
    cudaGetSymbolAddress(&p, g_gi_mol);    float* gi_mol = (float*)p;
    cudaGetSymbolAddress(&p, g_gh_mol);    float* gh_mol = (float*)p;
    cudaGetSymbolAddress(&p, g_molout);    float* molout = (float*)p;
    cudaGetSymbolAddress(&p, g_ssrc);      float* ssrc = (float*)p;
    cudaGetSymbolAddress(&p, g_vsrc);      float* vsrc = (float*)p;
    cudaGetSymbolAddress(&p, g_vdst);      float* vdst = (float*)p;
    cudaGetSymbolAddress(&p, g_whi);       __nv_bfloat16* whi = (__nv_bfloat16*)p;
    cudaGetSymbolAddress(&p, g_wlo);       __nv_bfloat16* wlo = (__nv_bfloat16*)p;
    cudaGetSymbolAddress(&p, g_xhi);       __nv_bfloat16* xhi = (__nv_bfloat16*)p;
    cudaGetSymbolAddress(&p, g_xlo);       __nv_bfloat16* xlo = (__nv_bfloat16*)p;
    cudaGetSymbolAddress(&p, g_phi);       __nv_bfloat16* phi = (__nv_bfloat16*)p;
    cudaGetSymbolAddress(&p, g_plo);       __nv_bfloat16* plo = (__nv_bfloat16*)p;
    cudaGetSymbolAddress(&p, g_ghi);       __nv_bfloat16* ghi = (__nv_bfloat16*)p;
    cudaGetSymbolAddress(&p, g_glo);       __nv_bfloat16* glo = (__nv_bfloat16*)p;
    cudaGetSymbolAddress(&p, g_qhi);       __nv_bfloat16* qhi = (__nv_bfloat16*)p;
    cudaGetSymbolAddress(&p, g_qlo);       __nv_bfloat16* qlo = (__nv_bfloat16*)p;
    float* outp = (float*)d_out;

    static cudaStream_t s1 = nullptr;
    static cudaEvent_t ev[8];
    if (s1 == nullptr) {
        cudaStreamCreateWithFlags(&s1, cudaStreamNonBlocking);
        for (int i = 0; i < 8; i++) cudaEventCreateWithFlags(&ev[i], cudaEventDisableTiming);
    }
    auto fork = [&](int i) {
        cudaEventRecord(ev[i], 0);
        cudaStreamWaitEvent(s1, ev[i], 0);
    };
    auto join = [&](int i) {
        cudaEventRecord(ev[i], s1);
        cudaStreamWaitEvent((cudaStream_t)0, ev[i], 0);
    };

    cudaFuncSetAttribute(k_gemm_tc, cudaFuncAttributeMaxDynamicSharedMemorySize, GEMM_SMEM);

    auto gemm = [&](const __nv_bfloat16* xh, const __nv_bfloat16* xl, int wrow,
                    float* Y, int M, int Nout) {
        int ntiles = (M + 127) / 128;
        int gy = Nout / 128;
        int gxmax = 148 / gy; if (gxmax < 1) gxmax = 1;
        int gx = ntiles < gxmax ? ntiles : gxmax;
        dim3 grid(gx, gy, 1);
        k_gemm_tc<<<grid, 256, GEMM_SMEM>>>(xh, xl, whi + (size_t)wrow * 128,
                                            wlo + (size_t)wrow * 128, Y, M, Nout,
                                            nullptr, nullptr, nullptr, nullptr, nullptr);
    };
    auto gemm2 = [&](const __nv_bfloat16* xh, const __nv_bfloat16* xl, int wrow, float* Y,
                     const __nv_bfloat16* xh2, const __nv_bfloat16* xl2, int wrow2, float* Y2,
                     int M, int Nout) {
        int ntiles = (M + 127) / 128;
        int gy = Nout / 128;
        int gxmax = 148 / (gy * 2); if (gxmax < 1) gxmax = 1;
        int gx = ntiles < gxmax ? ntiles : gxmax;
        dim3 grid(gx, gy, 2);
        k_gemm_tc<<<grid, 256, GEMM_SMEM>>>(xh, xl, whi + (size_t)wrow * 128,
                                            wlo + (size_t)wrow * 128, Y, M, Nout,
                                            xh2, xl2, whi + (size_t)wrow2 * 128,
                                            wlo + (size_t)wrow2 * 128, Y2);
    };

    // ===== phase 1: CSR build (s1)  ||  wsplit + gemm0(fp32 path) (main) =====
    fork(0);
    k_zero_int<<<(NN + 255) / 256, 256, 0, s1>>>(cnt, NN);
    k_hist<<<(EE + 255) / 256, 256, 0, s1>>>(adj_index, cnt);
    k_scan1<<<196, 1024, 0, s1>>>(cnt, rowoff, bsum, NN);
    k_scan2<<<1, 256, 0, s1>>>(bsum, 196);
    k_scan3<<<196, 1024, 0, s1>>>(rowoff, bsum, NN, EE, cursor);
    k_scatter<<<(EE + 255) / 256, 256, 0, s1>>>(adj_index, adj_value, cursor, col, val);
    k_segoff<<<(NN + 255) / 256, 256, 0, s1>>>(ttb, NN, NTTS, ttoff);
    k_segoff<<<(NTTS + 255) / 256, 256, 0, s1>>>(tgb, NTTS, NMOLS, moloff);
    k_vd<<<1, 128, 0, s1>>>(Wsrc, asrc, vsrc);
    k_vd<<<1, 128, 0, s1>>>(Wdst, adst, vdst);

    k_wsplit<<<1024, 256>>>(W_gcn, Wsrc, Wih, Whh, whi, wlo);
    gemm((const __nv_bfloat16*)node_attr, nullptr, WR_G0, t1, NN, 128);  // fp32 path
    join(1);

    // ===== GCN layers =====
    k_spmm<<<NN / 8, 256>>>(t1, nullptr, xhi, xlo, rowoff, col, val, b_gcn,
                            nullptr, nullptr, bg, bb, bm, bv, 0, -1, NN);
    gemm(xhi, xlo, WR_G1, t1, NN, 128);
    k_spmm<<<NN / 8, 256>>>(t1, t2, nullptr, nullptr, rowoff, col, val, b_gcn + CC,
                            vsrc, ssrc, bg, bb, bm, bv, 1, 2, NN);

    // ===== tt stage =====
    k_fusepool<<<(NTTS * 32 + 255) / 256, 256>>>(t2, ssrc, vdst, ttoff, NTTS,
                                                 meanbn_tt, phi, plo, qhi, qlo,
                                                 bg, bb, bm, bv, 3);
    gemm(qhi, qlo, WR_S0, hsTmp, NTTS, 128);
    k_elu<<<(NTTS * CC + 255) / 256, 256>>>(hsTmp, gbias, ghi, glo, NTTS * CC);
    gemm2(ghi, glo, WR_IH0, gi_tt, phi, plo, WR_HH0, gh_tt, NTTS, 384);
    k_gru<<<(NTTS * CC + 255) / 256, 256>>>(gi_tt, gh_tt, meanbn_tt, bih, bhh,
                                            ttbn, ghi, glo, NTTS, bg, bb, bm, bv, 4, 5);

    // ===== mol stage =====
    fork(4);
    k_vd<<<1, 128, 0, s1>>>(Wsrc + CC * CC, asrc + CC, vsrc);
    k_vd<<<1, 128, 0, s1>>>(Wdst + CC * CC, adst + CC, vdst);
    join(5);
    k_rowdot<<<(NTTS * 32 + 255) / 256, 256>>>(ttbn, vsrc, ssrc, NTTS);
    k_fusepool<<<(NMOLS * 32 + 255) / 256, 256>>>(ttbn, ssrc, vdst, moloff, NMOLS,
                                                  meanbn_mol, phi, plo, qhi, qlo,
                                                  bg, bb, bm, bv, 6);
    gemm(qhi, qlo, WR_S1, hsTmp, NMOLS, 128);
    k_elu<<<(NMOLS * CC + 255) / 256, 256>>>(hsTmp, gbias + CC, ghi, glo, NMOLS * CC);
    gemm2(ghi, glo, WR_IH1, gi_mol, phi, plo, WR_HH1, gh_mol, NMOLS, 384);
    k_gru<<<(NMOLS * CC + 255) / 256, 256>>>(gi_mol, gh_mol, meanbn_mol, bih + 3 * CC,
                                             bhh + 3 * CC, molout, nullptr, nullptr,
                                             NMOLS, bg, bb, bm, bv, 7, -1);

    // predictor
    k_pred<<<NMOLS, 64>>>(molout, pW1, pb1, pW2, pb2, outp);
}